// round 1
// baseline (speedup 1.0000x reference)
#include <cuda_runtime.h>
#include <math.h>

#define Cc     256
#define HW     16384
#define Bb     8
#define CHW    (Cc*HW)         // 4194304
#define NTOT   (Bb*HW)         // 131072
#define TOTAL  (Bb*CHW)        // 33554432
#define PROB_OFF TOTAL
#define NS     50

#define BM 128
#define BN 128
#define BK 16

// ---------------- scratch (device globals; no allocation) ----------------
__device__ float g_hpre[TOTAL];                 // 134 MB
__device__ float g_sum[Cc], g_sumsq[Cc];
__device__ float g_bna[Cc], g_bnb[Cc];
__device__ float g_mean[NTOT], g_logvar[NTOT], g_u[NTOT];
__device__ unsigned int g_minb, g_maxb;

// ---------------- init (must run every call: graph replay) ----------------
__global__ void k_init() {
    int t = threadIdx.x;
    if (t < Cc) { g_sum[t] = 0.f; g_sumsq[t] = 0.f; }
    if (t == 0) { g_minb = 0xFFFFFFFFu; g_maxb = 0u; }
}

// ---------------- GEMM1: hpre = W_proj @ x, + BN stats ----------------
__global__ __launch_bounds__(256, 2)
void k_gemm1(const float* __restrict__ x, const float* __restrict__ Wp) {
    __shared__ float As[BK][BM];
    __shared__ float Bs[BK][BN];
    __shared__ float s_sum[BM], s_sq[BM];

    const int b  = blockIdx.z;
    const int mo = blockIdx.y * BM;
    const int no = blockIdx.x * BN;
    const float* Bmat = x + (size_t)b * CHW;

    const int tid  = threadIdx.x;
    const int tm0  = (tid >> 4) << 3;
    const int tn0  = (tid & 15) << 3;
    const int a_row = tid >> 1, a_col = (tid & 1) << 3;
    const int b_row = tid >> 4, b_col = (tid & 15) << 3;

    if (tid < BM) { s_sum[tid] = 0.f; s_sq[tid] = 0.f; }

    float acc[8][8];
#pragma unroll
    for (int i = 0; i < 8; i++)
#pragma unroll
        for (int j = 0; j < 8; j++) acc[i][j] = 0.f;

    for (int k0 = 0; k0 < Cc; k0 += BK) {
        float4 av0 = *(const float4*)(Wp + (size_t)(mo + a_row) * Cc + k0 + a_col);
        float4 av1 = *(const float4*)(Wp + (size_t)(mo + a_row) * Cc + k0 + a_col + 4);
        As[a_col + 0][a_row] = av0.x; As[a_col + 1][a_row] = av0.y;
        As[a_col + 2][a_row] = av0.z; As[a_col + 3][a_row] = av0.w;
        As[a_col + 4][a_row] = av1.x; As[a_col + 5][a_row] = av1.y;
        As[a_col + 6][a_row] = av1.z; As[a_col + 7][a_row] = av1.w;
        float4 bv0 = *(const float4*)(Bmat + (size_t)(k0 + b_row) * HW + no + b_col);
        float4 bv1 = *(const float4*)(Bmat + (size_t)(k0 + b_row) * HW + no + b_col + 4);
        *(float4*)&Bs[b_row][b_col]     = bv0;
        *(float4*)&Bs[b_row][b_col + 4] = bv1;
        __syncthreads();
#pragma unroll
        for (int k = 0; k < BK; k++) {
            float ra[8], rb[8];
            *(float4*)(ra)     = *(const float4*)&As[k][tm0];
            *(float4*)(ra + 4) = *(const float4*)&As[k][tm0 + 4];
            *(float4*)(rb)     = *(const float4*)&Bs[k][tn0];
            *(float4*)(rb + 4) = *(const float4*)&Bs[k][tn0 + 4];
#pragma unroll
            for (int i = 0; i < 8; i++)
#pragma unroll
                for (int j = 0; j < 8; j++) acc[i][j] = fmaf(ra[i], rb[j], acc[i][j]);
        }
        __syncthreads();
    }

    float* outp = g_hpre + (size_t)b * CHW;
#pragma unroll
    for (int i = 0; i < 8; i++) {
        int row = mo + tm0 + i;
        size_t base = (size_t)row * HW + no + tn0;
        *(float4*)(outp + base)     = *(float4*)&acc[i][0];
        *(float4*)(outp + base + 4) = *(float4*)&acc[i][4];
        float rs = 0.f, rq = 0.f;
#pragma unroll
        for (int j = 0; j < 8; j++) { rs += acc[i][j]; rq += acc[i][j] * acc[i][j]; }
        atomicAdd(&s_sum[tm0 + i], rs);
        atomicAdd(&s_sq[tm0 + i], rq);
    }
    __syncthreads();
    if (tid < BM) {
        atomicAdd(&g_sum[mo + tid],   s_sum[tid]);
        atomicAdd(&g_sumsq[mo + tid], s_sq[tid]);
    }
}

// ---------------- BN finalize ----------------
__global__ void k_bnfin(const float* __restrict__ gamma, const float* __restrict__ beta) {
    int c = threadIdx.x;
    float n   = (float)NTOT;
    float mu  = g_sum[c] / n;
    float var = fmaxf(g_sumsq[c] / n - mu * mu, 0.f);
    float inv = rsqrtf(var + 1e-5f);
    float a   = gamma[c] * inv;
    g_bna[c] = a;
    g_bnb[c] = beta[c] - mu * a;
}

// ---------------- GEMM2: residual = W_conv @ relu(bn(hpre)) + b; also W_mean/W_std dots ----------------
__global__ __launch_bounds__(256)
void k_gemm2(const float* __restrict__ Wc, const float* __restrict__ bconv,
             const float* __restrict__ Wm, const float* __restrict__ Ws,
             float* __restrict__ out) {
    __shared__ float As[BK][BM];
    __shared__ float Bs[BK][BN];
    __shared__ float s_wm[Cc], s_ws[Cc];

    const int b  = blockIdx.z;
    const int mo = blockIdx.y * BM;
    const int no = blockIdx.x * BN;
    const float* Bmat = g_hpre + (size_t)b * CHW;

    const int tid  = threadIdx.x;
    const int tm0  = (tid >> 4) << 3;
    const int tn0  = (tid & 15) << 3;
    const int a_row = tid >> 1, a_col = (tid & 1) << 3;
    const int b_row = tid >> 4, b_col = (tid & 15) << 3;

    s_wm[tid] = Wm[tid];
    s_ws[tid] = Ws[tid];

    const bool aux = (blockIdx.y == 0) && (tid < 16);

    float acc[8][8];
#pragma unroll
    for (int i = 0; i < 8; i++)
#pragma unroll
        for (int j = 0; j < 8; j++) acc[i][j] = 0.f;
    float macc[8] = {0.f,0.f,0.f,0.f,0.f,0.f,0.f,0.f};
    float lacc[8] = {0.f,0.f,0.f,0.f,0.f,0.f,0.f,0.f};

    for (int k0 = 0; k0 < Cc; k0 += BK) {
        float4 av0 = *(const float4*)(Wc + (size_t)(mo + a_row) * Cc + k0 + a_col);
        float4 av1 = *(const float4*)(Wc + (size_t)(mo + a_row) * Cc + k0 + a_col + 4);
        As[a_col + 0][a_row] = av0.x; As[a_col + 1][a_row] = av0.y;
        As[a_col + 2][a_row] = av0.z; As[a_col + 3][a_row] = av0.w;
        As[a_col + 4][a_row] = av1.x; As[a_col + 5][a_row] = av1.y;
        As[a_col + 6][a_row] = av1.z; As[a_col + 7][a_row] = av1.w;
        int c = k0 + b_row;
        float ba = g_bna[c], bb = g_bnb[c];
        float4 bv0 = *(const float4*)(Bmat + (size_t)c * HW + no + b_col);
        float4 bv1 = *(const float4*)(Bmat + (size_t)c * HW + no + b_col + 4);
        bv0.x = fmaxf(fmaf(ba, bv0.x, bb), 0.f); bv0.y = fmaxf(fmaf(ba, bv0.y, bb), 0.f);
        bv0.z = fmaxf(fmaf(ba, bv0.z, bb), 0.f); bv0.w = fmaxf(fmaf(ba, bv0.w, bb), 0.f);
        bv1.x = fmaxf(fmaf(ba, bv1.x, bb), 0.f); bv1.y = fmaxf(fmaf(ba, bv1.y, bb), 0.f);
        bv1.z = fmaxf(fmaf(ba, bv1.z, bb), 0.f); bv1.w = fmaxf(fmaf(ba, bv1.w, bb), 0.f);
        *(float4*)&Bs[b_row][b_col]     = bv0;
        *(float4*)&Bs[b_row][b_col + 4] = bv1;
        __syncthreads();
#pragma unroll
        for (int k = 0; k < BK; k++) {
            float ra[8], rb[8];
            *(float4*)(ra)     = *(const float4*)&As[k][tm0];
            *(float4*)(ra + 4) = *(const float4*)&As[k][tm0 + 4];
            *(float4*)(rb)     = *(const float4*)&Bs[k][tn0];
            *(float4*)(rb + 4) = *(const float4*)&Bs[k][tn0 + 4];
#pragma unroll
            for (int i = 0; i < 8; i++)
#pragma unroll
                for (int j = 0; j < 8; j++) acc[i][j] = fmaf(ra[i], rb[j], acc[i][j]);
            if (aux) {
                float wm = s_wm[k0 + k], ws = s_ws[k0 + k];
#pragma unroll
                for (int j = 0; j < 8; j++) {
                    macc[j] = fmaf(wm, rb[j], macc[j]);
                    lacc[j] = fmaf(ws, rb[j], lacc[j]);
                }
            }
        }
        __syncthreads();
    }

    float* outp = out + (size_t)b * CHW;
#pragma unroll
    for (int i = 0; i < 8; i++) {
        int row = mo + tm0 + i;
        float bc = bconv[row];
        size_t base = (size_t)row * HW + no + tn0;
        float4 o0, o1;
        o0.x = acc[i][0] + bc; o0.y = acc[i][1] + bc; o0.z = acc[i][2] + bc; o0.w = acc[i][3] + bc;
        o1.x = acc[i][4] + bc; o1.y = acc[i][5] + bc; o1.z = acc[i][6] + bc; o1.w = acc[i][7] + bc;
        *(float4*)(outp + base)     = o0;
        *(float4*)(outp + base + 4) = o1;
    }
    if (aux) {
        size_t base = (size_t)b * HW + no + tn0;
#pragma unroll
        for (int j = 0; j < 8; j++) {
            g_mean[base + j]   = macc[j];
            g_logvar[base + j] = lacc[j];
        }
    }
}

// ---------------- per-pixel: prob_x, u = unbiased var of 50 sigmoid samples ----------------
__global__ void k_prob(const float* __restrict__ eps1, const float* __restrict__ eps50,
                       float* __restrict__ out) {
    int p = blockIdx.x * blockDim.x + threadIdx.x;
    if (p >= NTOT) return;
    int b  = p >> 14;
    int hw = p & (HW - 1);
    float mean = g_mean[p];
    float stdv = expf(0.5f * g_logvar[p]);
    out[PROB_OFF + p] = fmaf(eps1[p], stdv, mean);

    const float* e = eps50 + (size_t)b * NS * HW + hw;
    float v[NS];
    float s = 0.f;
#pragma unroll
    for (int i = 0; i < NS; i++) {
        float t  = fmaf(e[(size_t)i * HW], stdv, mean);
        float pv = 1.f / (1.f + expf(-t));
        v[i] = pv; s += pv;
    }
    float m = s * (1.f / NS);
    float ss = 0.f;
#pragma unroll
    for (int i = 0; i < NS; i++) { float d = v[i] - m; ss = fmaf(d, d, ss); }
    g_u[p] = ss * (1.f / (NS - 1));
}

// ---------------- 3x (7x7 box filter) per image, + global min/max ----------------
__global__ void k_box() {
    extern __shared__ float sm[];
    float* s0 = sm;
    float* s1 = sm + HW;
    __shared__ unsigned int smn, smx;
    const int b = blockIdx.x;
    const int tid = threadIdx.x;
    const int nth = blockDim.x;
    if (tid == 0) { smn = 0xFFFFFFFFu; smx = 0u; }

    for (int i = tid; i < HW; i += nth) s0[i] = g_u[(size_t)b * HW + i];
    __syncthreads();

    for (int it = 0; it < 3; it++) {
        // horizontal 7-tap (zero pad)
        for (int i = tid; i < HW; i += nth) {
            int y = i >> 7, x = i & 127;
            int x0 = x - 3 < 0 ? 0 : x - 3;
            int x1 = x + 3 > 127 ? 127 : x + 3;
            float s = 0.f;
            for (int xx = x0; xx <= x1; xx++) s += s0[(y << 7) + xx];
            s1[i] = s;
        }
        __syncthreads();
        // vertical 7-tap
        for (int i = tid; i < HW; i += nth) {
            int y = i >> 7, x = i & 127;
            int y0 = y - 3 < 0 ? 0 : y - 3;
            int y1 = y + 3 > 127 ? 127 : y + 3;
            float s = 0.f;
            for (int yy = y0; yy <= y1; yy++) s += s1[(yy << 7) + x];
            s0[i] = s;
        }
        __syncthreads();
    }

    float lmn = 3.4e38f, lmx = -3.4e38f;
    for (int i = tid; i < HW; i += nth) {
        float v = s0[i];
        g_u[(size_t)b * HW + i] = v;
        lmn = fminf(lmn, v); lmx = fmaxf(lmx, v);
    }
    // values are >= 0, so float bits order as uints
    atomicMin(&smn, __float_as_uint(lmn));
    atomicMax(&smx, __float_as_uint(lmx));
    __syncthreads();
    if (tid == 0) {
        atomicMin(&g_minb, smn);
        atomicMax(&g_maxb, smx);
    }
}

// ---------------- final scaling of residual ----------------
__global__ void k_final(const float* __restrict__ randu, float* __restrict__ out) {
    int i = blockIdx.x * blockDim.x + threadIdx.x;       // float4 index
    if (i >= TOTAL / 4) return;
    float mn = __uint_as_float(g_minb);
    float mx = __uint_as_float(g_maxb);
    float inv = 1.f / (mx - mn);
    int b = i / (CHW / 4);
    int n = (i & (HW / 4 - 1)) << 2;
    size_t ub = (size_t)b * HW + n;
    float4 u4 = *(const float4*)&g_u[ub];
    float4 r4 = *(const float4*)&randu[ub];
    float4 o  = ((float4*)out)[i];
    float u;
    u = (u4.x - mn) * inv; o.x *= (1.f - u) * (u < r4.x ? 1.f : 0.f);
    u = (u4.y - mn) * inv; o.y *= (1.f - u) * (u < r4.y ? 1.f : 0.f);
    u = (u4.z - mn) * inv; o.z *= (1.f - u) * (u < r4.z ? 1.f : 0.f);
    u = (u4.w - mn) * inv; o.w *= (1.f - u) * (u < r4.w ? 1.f : 0.f);
    ((float4*)out)[i] = o;
}

// ---------------- launch ----------------
extern "C" void kernel_launch(void* const* d_in, const int* in_sizes, int n_in,
                              void* d_out, int out_size) {
    const float* x      = (const float*)d_in[0];
    const float* Wproj  = (const float*)d_in[1];
    const float* gamma  = (const float*)d_in[2];
    const float* beta   = (const float*)d_in[3];
    const float* Wconv  = (const float*)d_in[4];
    const float* bconv  = (const float*)d_in[5];
    const float* Wmean  = (const float*)d_in[6];
    const float* Wstd   = (const float*)d_in[7];
    const float* eps1   = (const float*)d_in[8];
    const float* eps50  = (const float*)d_in[9];
    const float* randu  = (const float*)d_in[10];
    float* out = (float*)d_out;

    cudaFuncSetAttribute(k_box, cudaFuncAttributeMaxDynamicSharedMemorySize, 2 * HW * 4);

    k_init<<<1, 256>>>();
    dim3 g(HW / BN, Cc / BM, Bb);
    k_gemm1<<<g, 256>>>(x, Wproj);
    k_bnfin<<<1, Cc>>>(gamma, beta);
    k_gemm2<<<g, 256>>>(Wconv, bconv, Wmean, Wstd, out);
    k_prob<<<NTOT / 256, 256>>>(eps1, eps50, out);
    k_box<<<Bb, 1024, 2 * HW * 4>>>();
    k_final<<<(TOTAL / 4 + 255) / 256, 256>>>(randu, out);
}

// round 2
// speedup vs baseline: 1.0004x; 1.0004x over previous
#include <cuda_runtime.h>
#include <math.h>

#define Cc     256
#define HW     16384
#define Bb     8
#define CHW    (Cc*HW)         // 4194304
#define NTOT   (Bb*HW)         // 131072
#define TOTAL  (Bb*CHW)        // 33554432
#define PROB_OFF TOTAL
#define NS     50

#define BM 128
#define BN 128
#define BK 16

// ---------------- scratch (device globals; no allocation) ----------------
__device__ float g_hpre[TOTAL];                 // 134 MB
__device__ float g_sum[Cc], g_sumsq[Cc];
__device__ float g_bna[Cc], g_bnb[Cc];
__device__ float g_mean[NTOT], g_logvar[NTOT], g_u[NTOT];
__device__ unsigned int g_minb, g_maxb;

// ---------------- init (must run every call: graph replay) ----------------
__global__ void k_init() {
    int t = threadIdx.x;
    if (t < Cc) { g_sum[t] = 0.f; g_sumsq[t] = 0.f; }
    if (t == 0) { g_minb = 0xFFFFFFFFu; g_maxb = 0u; }
}

// ---------------- GEMM1: hpre = W_proj @ x, + BN stats ----------------
__global__ __launch_bounds__(256, 2)
void k_gemm1(const float* __restrict__ x, const float* __restrict__ Wp) {
    __shared__ float As[BK][BM];
    __shared__ float Bs[BK][BN];
    __shared__ float s_sum[BM], s_sq[BM];

    const int b  = blockIdx.z;
    const int mo = blockIdx.y * BM;
    const int no = blockIdx.x * BN;
    const float* Bmat = x + (size_t)b * CHW;

    const int tid  = threadIdx.x;
    const int tm0  = (tid >> 4) << 3;
    const int tn0  = (tid & 15) << 3;
    const int a_row = tid >> 1, a_col = (tid & 1) << 3;
    const int b_row = tid >> 4, b_col = (tid & 15) << 3;

    if (tid < BM) { s_sum[tid] = 0.f; s_sq[tid] = 0.f; }

    float acc[8][8];
#pragma unroll
    for (int i = 0; i < 8; i++)
#pragma unroll
        for (int j = 0; j < 8; j++) acc[i][j] = 0.f;

    for (int k0 = 0; k0 < Cc; k0 += BK) {
        float4 av0 = *(const float4*)(Wp + (size_t)(mo + a_row) * Cc + k0 + a_col);
        float4 av1 = *(const float4*)(Wp + (size_t)(mo + a_row) * Cc + k0 + a_col + 4);
        As[a_col + 0][a_row] = av0.x; As[a_col + 1][a_row] = av0.y;
        As[a_col + 2][a_row] = av0.z; As[a_col + 3][a_row] = av0.w;
        As[a_col + 4][a_row] = av1.x; As[a_col + 5][a_row] = av1.y;
        As[a_col + 6][a_row] = av1.z; As[a_col + 7][a_row] = av1.w;
        float4 bv0 = *(const float4*)(Bmat + (size_t)(k0 + b_row) * HW + no + b_col);
        float4 bv1 = *(const float4*)(Bmat + (size_t)(k0 + b_row) * HW + no + b_col + 4);
        *(float4*)&Bs[b_row][b_col]     = bv0;
        *(float4*)&Bs[b_row][b_col + 4] = bv1;
        __syncthreads();
#pragma unroll
        for (int k = 0; k < BK; k++) {
            float ra[8], rb[8];
            *(float4*)(ra)     = *(const float4*)&As[k][tm0];
            *(float4*)(ra + 4) = *(const float4*)&As[k][tm0 + 4];
            *(float4*)(rb)     = *(const float4*)&Bs[k][tn0];
            *(float4*)(rb + 4) = *(const float4*)&Bs[k][tn0 + 4];
#pragma unroll
            for (int i = 0; i < 8; i++)
#pragma unroll
                for (int j = 0; j < 8; j++) acc[i][j] = fmaf(ra[i], rb[j], acc[i][j]);
        }
        __syncthreads();
    }

    float* outp = g_hpre + (size_t)b * CHW;
#pragma unroll
    for (int i = 0; i < 8; i++) {
        int row = mo + tm0 + i;
        size_t base = (size_t)row * HW + no + tn0;
        *(float4*)(outp + base)     = *(float4*)&acc[i][0];
        *(float4*)(outp + base + 4) = *(float4*)&acc[i][4];
        float rs = 0.f, rq = 0.f;
#pragma unroll
        for (int j = 0; j < 8; j++) { rs += acc[i][j]; rq += acc[i][j] * acc[i][j]; }
        atomicAdd(&s_sum[tm0 + i], rs);
        atomicAdd(&s_sq[tm0 + i], rq);
    }
    __syncthreads();
    if (tid < BM) {
        atomicAdd(&g_sum[mo + tid],   s_sum[tid]);
        atomicAdd(&g_sumsq[mo + tid], s_sq[tid]);
    }
}

// ---------------- BN finalize ----------------
__global__ void k_bnfin(const float* __restrict__ gamma, const float* __restrict__ beta) {
    int c = threadIdx.x;
    float n   = (float)NTOT;
    float mu  = g_sum[c] / n;
    float var = fmaxf(g_sumsq[c] / n - mu * mu, 0.f);
    float inv = rsqrtf(var + 1e-5f);
    float a   = gamma[c] * inv;
    g_bna[c] = a;
    g_bnb[c] = beta[c] - mu * a;
}

// ---------------- GEMM2: residual = W_conv @ relu(bn(hpre)) + b; also W_mean/W_std dots ----------------
__global__ __launch_bounds__(256)
void k_gemm2(const float* __restrict__ Wc, const float* __restrict__ bconv,
             const float* __restrict__ Wm, const float* __restrict__ Ws,
             float* __restrict__ out) {
    __shared__ float As[BK][BM];
    __shared__ float Bs[BK][BN];
    __shared__ float s_wm[Cc], s_ws[Cc];

    const int b  = blockIdx.z;
    const int mo = blockIdx.y * BM;
    const int no = blockIdx.x * BN;
    const float* Bmat = g_hpre + (size_t)b * CHW;

    const int tid  = threadIdx.x;
    const int tm0  = (tid >> 4) << 3;
    const int tn0  = (tid & 15) << 3;
    const int a_row = tid >> 1, a_col = (tid & 1) << 3;
    const int b_row = tid >> 4, b_col = (tid & 15) << 3;

    s_wm[tid] = Wm[tid];
    s_ws[tid] = Ws[tid];

    const bool aux = (blockIdx.y == 0) && (tid < 16);

    float acc[8][8];
#pragma unroll
    for (int i = 0; i < 8; i++)
#pragma unroll
        for (int j = 0; j < 8; j++) acc[i][j] = 0.f;
    float macc[8] = {0.f,0.f,0.f,0.f,0.f,0.f,0.f,0.f};
    float lacc[8] = {0.f,0.f,0.f,0.f,0.f,0.f,0.f,0.f};

    for (int k0 = 0; k0 < Cc; k0 += BK) {
        float4 av0 = *(const float4*)(Wc + (size_t)(mo + a_row) * Cc + k0 + a_col);
        float4 av1 = *(const float4*)(Wc + (size_t)(mo + a_row) * Cc + k0 + a_col + 4);
        As[a_col + 0][a_row] = av0.x; As[a_col + 1][a_row] = av0.y;
        As[a_col + 2][a_row] = av0.z; As[a_col + 3][a_row] = av0.w;
        As[a_col + 4][a_row] = av1.x; As[a_col + 5][a_row] = av1.y;
        As[a_col + 6][a_row] = av1.z; As[a_col + 7][a_row] = av1.w;
        int c = k0 + b_row;
        float ba = g_bna[c], bb = g_bnb[c];
        float4 bv0 = *(const float4*)(Bmat + (size_t)c * HW + no + b_col);
        float4 bv1 = *(const float4*)(Bmat + (size_t)c * HW + no + b_col + 4);
        bv0.x = fmaxf(fmaf(ba, bv0.x, bb), 0.f); bv0.y = fmaxf(fmaf(ba, bv0.y, bb), 0.f);
        bv0.z = fmaxf(fmaf(ba, bv0.z, bb), 0.f); bv0.w = fmaxf(fmaf(ba, bv0.w, bb), 0.f);
        bv1.x = fmaxf(fmaf(ba, bv1.x, bb), 0.f); bv1.y = fmaxf(fmaf(ba, bv1.y, bb), 0.f);
        bv1.z = fmaxf(fmaf(ba, bv1.z, bb), 0.f); bv1.w = fmaxf(fmaf(ba, bv1.w, bb), 0.f);
        *(float4*)&Bs[b_row][b_col]     = bv0;
        *(float4*)&Bs[b_row][b_col + 4] = bv1;
        __syncthreads();
#pragma unroll
        for (int k = 0; k < BK; k++) {
            float ra[8], rb[8];
            *(float4*)(ra)     = *(const float4*)&As[k][tm0];
            *(float4*)(ra + 4) = *(const float4*)&As[k][tm0 + 4];
            *(float4*)(rb)     = *(const float4*)&Bs[k][tn0];
            *(float4*)(rb + 4) = *(const float4*)&Bs[k][tn0 + 4];
#pragma unroll
            for (int i = 0; i < 8; i++)
#pragma unroll
                for (int j = 0; j < 8; j++) acc[i][j] = fmaf(ra[i], rb[j], acc[i][j]);
            if (aux) {
                float wm = s_wm[k0 + k], ws = s_ws[k0 + k];
#pragma unroll
                for (int j = 0; j < 8; j++) {
                    macc[j] = fmaf(wm, rb[j], macc[j]);
                    lacc[j] = fmaf(ws, rb[j], lacc[j]);
                }
            }
        }
        __syncthreads();
    }

    float* outp = out + (size_t)b * CHW;
#pragma unroll
    for (int i = 0; i < 8; i++) {
        int row = mo + tm0 + i;
        float bc = bconv[row];
        size_t base = (size_t)row * HW + no + tn0;
        float4 o0, o1;
        o0.x = acc[i][0] + bc; o0.y = acc[i][1] + bc; o0.z = acc[i][2] + bc; o0.w = acc[i][3] + bc;
        o1.x = acc[i][4] + bc; o1.y = acc[i][5] + bc; o1.z = acc[i][6] + bc; o1.w = acc[i][7] + bc;
        *(float4*)(outp + base)     = o0;
        *(float4*)(outp + base + 4) = o1;
    }
    if (aux) {
        size_t base = (size_t)b * HW + no + tn0;
#pragma unroll
        for (int j = 0; j < 8; j++) {
            g_mean[base + j]   = macc[j];
            g_logvar[base + j] = lacc[j];
        }
    }
}

// ---------------- per-pixel: prob_x, u = unbiased var of 50 sigmoid samples ----------------
__global__ void k_prob(const float* __restrict__ eps1, const float* __restrict__ eps50,
                       float* __restrict__ out) {
    int p = blockIdx.x * blockDim.x + threadIdx.x;
    if (p >= NTOT) return;
    int b  = p >> 14;
    int hw = p & (HW - 1);
    float mean = g_mean[p];
    float stdv = expf(0.5f * g_logvar[p]);
    out[PROB_OFF + p] = fmaf(eps1[p], stdv, mean);

    const float* e = eps50 + (size_t)b * NS * HW + hw;
    float v[NS];
    float s = 0.f;
#pragma unroll
    for (int i = 0; i < NS; i++) {
        float t  = fmaf(e[(size_t)i * HW], stdv, mean);
        float pv = 1.f / (1.f + expf(-t));
        v[i] = pv; s += pv;
    }
    float m = s * (1.f / NS);
    float ss = 0.f;
#pragma unroll
    for (int i = 0; i < NS; i++) { float d = v[i] - m; ss = fmaf(d, d, ss); }
    g_u[p] = ss * (1.f / (NS - 1));
}

// ---------------- 3x (7x7 box filter) per image, + global min/max ----------------
__global__ void k_box() {
    extern __shared__ float sm[];
    float* s0 = sm;
    float* s1 = sm + HW;
    __shared__ unsigned int smn, smx;
    const int b = blockIdx.x;
    const int tid = threadIdx.x;
    const int nth = blockDim.x;
    if (tid == 0) { smn = 0xFFFFFFFFu; smx = 0u; }

    for (int i = tid; i < HW; i += nth) s0[i] = g_u[(size_t)b * HW + i];
    __syncthreads();

    for (int it = 0; it < 3; it++) {
        // horizontal 7-tap (zero pad)
        for (int i = tid; i < HW; i += nth) {
            int y = i >> 7, x = i & 127;
            int x0 = x - 3 < 0 ? 0 : x - 3;
            int x1 = x + 3 > 127 ? 127 : x + 3;
            float s = 0.f;
            for (int xx = x0; xx <= x1; xx++) s += s0[(y << 7) + xx];
            s1[i] = s;
        }
        __syncthreads();
        // vertical 7-tap
        for (int i = tid; i < HW; i += nth) {
            int y = i >> 7, x = i & 127;
            int y0 = y - 3 < 0 ? 0 : y - 3;
            int y1 = y + 3 > 127 ? 127 : y + 3;
            float s = 0.f;
            for (int yy = y0; yy <= y1; yy++) s += s1[(yy << 7) + x];
            s0[i] = s;
        }
        __syncthreads();
    }

    float lmn = 3.4e38f, lmx = -3.4e38f;
    for (int i = tid; i < HW; i += nth) {
        float v = s0[i];
        g_u[(size_t)b * HW + i] = v;
        lmn = fminf(lmn, v); lmx = fmaxf(lmx, v);
    }
    // values are >= 0, so float bits order as uints
    atomicMin(&smn, __float_as_uint(lmn));
    atomicMax(&smx, __float_as_uint(lmx));
    __syncthreads();
    if (tid == 0) {
        atomicMin(&g_minb, smn);
        atomicMax(&g_maxb, smx);
    }
}

// ---------------- final scaling of residual ----------------
__global__ void k_final(const float* __restrict__ randu, float* __restrict__ out) {
    int i = blockIdx.x * blockDim.x + threadIdx.x;       // float4 index
    if (i >= TOTAL / 4) return;
    float mn = __uint_as_float(g_minb);
    float mx = __uint_as_float(g_maxb);
    float inv = 1.f / (mx - mn);
    int b = i / (CHW / 4);
    int n = (i & (HW / 4 - 1)) << 2;
    size_t ub = (size_t)b * HW + n;
    float4 u4 = *(const float4*)&g_u[ub];
    float4 r4 = *(const float4*)&randu[ub];
    float4 o  = ((float4*)out)[i];
    float u;
    u = (u4.x - mn) * inv; o.x *= (1.f - u) * (u < r4.x ? 1.f : 0.f);
    u = (u4.y - mn) * inv; o.y *= (1.f - u) * (u < r4.y ? 1.f : 0.f);
    u = (u4.z - mn) * inv; o.z *= (1.f - u) * (u < r4.z ? 1.f : 0.f);
    u = (u4.w - mn) * inv; o.w *= (1.f - u) * (u < r4.w ? 1.f : 0.f);
    ((float4*)out)[i] = o;
}

// ---------------- launch ----------------
extern "C" void kernel_launch(void* const* d_in, const int* in_sizes, int n_in,
                              void* d_out, int out_size) {
    const float* x      = (const float*)d_in[0];
    const float* Wproj  = (const float*)d_in[1];
    const float* gamma  = (const float*)d_in[2];
    const float* beta   = (const float*)d_in[3];
    const float* Wconv  = (const float*)d_in[4];
    const float* bconv  = (const float*)d_in[5];
    const float* Wmean  = (const float*)d_in[6];
    const float* Wstd   = (const float*)d_in[7];
    const float* eps1   = (const float*)d_in[8];
    const float* eps50  = (const float*)d_in[9];
    const float* randu  = (const float*)d_in[10];
    float* out = (float*)d_out;

    cudaFuncSetAttribute(k_box, cudaFuncAttributeMaxDynamicSharedMemorySize, 2 * HW * 4);

    k_init<<<1, 256>>>();
    dim3 g(HW / BN, Cc / BM, Bb);
    k_gemm1<<<g, 256>>>(x, Wproj);
    k_bnfin<<<1, Cc>>>(gamma, beta);
    k_gemm2<<<g, 256>>>(Wconv, bconv, Wmean, Wstd, out);
    k_prob<<<NTOT / 256, 256>>>(eps1, eps50, out);
    k_box<<<Bb, 1024, 2 * HW * 4>>>();
    k_final<<<(TOTAL / 4 + 255) / 256, 256>>>(randu, out);
}

// round 4
// speedup vs baseline: 1.4039x; 1.4033x over previous
#include <cuda_runtime.h>
#include <cuda_bf16.h>
#include <math.h>
#include <stdint.h>

#define Cc 256
#define HW 16384
#define Bb 8
#define CHW (Cc*HW)
#define NTOT (Bb*HW)
#define TOTAL (Bb*CHW)
#define PROB_OFF TOTAL
#define NS 50

#define STG 36864            // bytes per stage: A 24KB + B 12KB
#define FAC_OFF (2*STG)      // 73728
#define BIAS_OFF (FAC_OFF+512)
#define SMEM_GEMM (BIAS_OFF+1024)

// ---------------- device globals ----------------
__device__ float g_h[TOTAL];                       // h pre-BN, [ch][P] fp32
__device__ __nv_bfloat16 g_h2hi[TOTAL], g_h2lo[TOTAL];  // bn-relu(h) split, [ch][P]
__device__ __nv_bfloat16 g_wA[2*3*Cc*Cc];          // weights split+swizzled per chunk
__device__ float g_sum[Cc], g_sumsq[Cc], g_bna[Cc], g_bnb[Cc];
__device__ float g_u[NTOT];
__device__ unsigned int g_minb, g_maxb;

union B8 { __nv_bfloat16 h[8]; uint4 v; };

__device__ __forceinline__ uint32_t s2u(const void* p) {
    uint32_t a;
    asm("{ .reg .u64 t; cvta.to.shared.u64 t, %1; cvt.u32.u64 %0, t; }" : "=r"(a) : "l"(p));
    return a;
}
__device__ __forceinline__ void cpa16(uint32_t dst, const void* src) {
    asm volatile("cp.async.cg.shared.global [%0], [%1], 16;" :: "r"(dst), "l"(src));
}
__device__ __forceinline__ void ldmx4(uint32_t& a0, uint32_t& a1, uint32_t& a2, uint32_t& a3, uint32_t ad) {
    asm volatile("ldmatrix.sync.aligned.m8n8.x4.shared.b16 {%0,%1,%2,%3}, [%4];"
                 : "=r"(a0), "=r"(a1), "=r"(a2), "=r"(a3) : "r"(ad));
}
__device__ __forceinline__ void ldmx2(uint32_t& b0, uint32_t& b1, uint32_t ad) {
    asm volatile("ldmatrix.sync.aligned.m8n8.x2.shared.b16 {%0,%1}, [%2];"
                 : "=r"(b0), "=r"(b1) : "r"(ad));
}
__device__ __forceinline__ void mma16816(float* d, const uint32_t* a, uint32_t b0, uint32_t b1) {
    asm volatile("mma.sync.aligned.m16n8k16.row.col.f32.bf16.bf16.f32 "
                 "{%0,%1,%2,%3}, {%4,%5,%6,%7}, {%8,%9}, {%0,%1,%2,%3};"
                 : "+f"(d[0]), "+f"(d[1]), "+f"(d[2]), "+f"(d[3])
                 : "r"(a[0]), "r"(a[1]), "r"(a[2]), "r"(a[3]), "r"(b0), "r"(b1));
}

// ---------------- init ----------------
__global__ void k_init() {
    int t = threadIdx.x;
    if (t < Cc) { g_sum[t] = 0.f; g_sumsq[t] = 0.f; }
    if (t == 0) { g_minb = 0xFFFFFFFFu; g_maxb = 0u; }
}

// ---------------- weight prep: 3-way split, chunked+swizzled ----------------
__global__ void k_prep_w(const float* __restrict__ Wp, const float* __restrict__ Wc) {
    int idx = blockIdx.x * blockDim.x + threadIdx.x;   // 0..131071
    int g = idx >> 16, ch = (idx >> 8) & 255, k = idx & 255;
    float w = (g ? Wc : Wp)[ch * Cc + k];
    __nv_bfloat16 H = __float2bfloat16(w);
    float r = w - __bfloat162float(H);
    __nv_bfloat16 M = __float2bfloat16(r);
    __nv_bfloat16 L = __float2bfloat16(r - __bfloat162float(M));
    int kc = k >> 4, kk = k & 15;
    int unit = ((kk >> 3) ^ (ch >> 2)) & 1;
    int elem = (ch * 32 + unit * 16 + (kk & 7) * 2) >> 1;
    size_t base = (size_t)((g * 3) * 16 + kc) * 4096 + elem;
    g_wA[base]          = H;
    g_wA[base + 65536]  = M;    // part stride = 16 chunks * 4096
    g_wA[base + 131072] = L;
}

// ---------------- mma.sync GEMM: tile 256ch x 128pix, K=256 in 16 chunks ----------------
// G=1: B = x fp32 (3-way split, 6 terms), epilogue -> g_h + BN stats
// G=2: B = g_h2 hi/lo (3 terms), epilogue -> out with bias + (1-u)*mask
template<int G>
__global__ __launch_bounds__(256, 1)
void k_gemm(const float* __restrict__ x, float* __restrict__ out,
            const float* __restrict__ bconv, const float* __restrict__ randu) {
    extern __shared__ __align__(16) char sm[];
    const uint32_t sb = s2u(sm);
    const int t = threadIdx.x, wid = t >> 5, lane = t & 31;
    const int P0 = blockIdx.x * 128;
    constexpr int PA = (G == 1) ? 3 : 2;
    constexpr int PB = (G == 1) ? 3 : 2;

    const int ch0 = (wid >> 1) * 64;
    const int pix0w = (wid & 1) * 64;
    const int aRow = lane & 15, aUnit = lane >> 4;
    const int l15 = lane & 15;
    const int bRowOff = l15 & 7, bUnit = (l15 >> 3) & 1;

    float* s_fac = (float*)(sm + FAC_OFF);
    float* s_bias = (float*)(sm + BIAS_OFF);
    if (G == 2) {
        if (t < 128) {
            float mn = __uint_as_float(g_minb), mx = __uint_as_float(g_maxb);
            float un = (g_u[P0 + t] - mn) / (mx - mn);
            s_fac[t] = (1.f - un) * ((un < randu[P0 + t]) ? 1.f : 0.f);
        }
        s_bias[t] = bconv[t];
    }

    float d[4][8][4];
#pragma unroll
    for (int i = 0; i < 4; i++)
#pragma unroll
        for (int j = 0; j < 8; j++)
#pragma unroll
            for (int e = 0; e < 4; e++) d[i][j][e] = 0.f;

    float bf[16];
    __nv_bfloat16 bh[16], bl[16];
    const float* xs = x + (size_t)(P0 >> 14) * CHW + (P0 & 16383) + t;

    // ---- loader helpers (inline via macros over c/stage) ----
#define ISSUE_A(cc, so) do { \
    _Pragma("unroll") \
    for (int i = 0; i < PA * 2; i++) { \
        int u = t + i * 256; \
        int p = u >> 9, w = u & 511; \
        const char* src = (const char*)g_wA + (size_t)(((G - 1) * 3 + p) * 16 + (cc)) * 8192 + w * 16; \
        cpa16(sb + (so) + p * 8192 + w * 16, src); \
    } \
    asm volatile("cp.async.commit_group;"); \
} while (0)

#define LOAD_B(cc) do { \
    if (G == 1) { \
        _Pragma("unroll") \
        for (int k = 0; k < 16; k++) bf[k] = xs[(size_t)((cc) * 16 + k) * HW]; \
    } else { \
        _Pragma("unroll") \
        for (int k = 0; k < 16; k++) { \
            size_t o = (size_t)((cc) * 16 + k) * NTOT + P0 + t; \
            bh[k] = g_h2hi[o]; bl[k] = g_h2lo[o]; \
        } \
    } \
} while (0)

#define STORE_B(so) do { \
    _Pragma("unroll") \
    for (int half = 0; half < 2; half++) { \
        int u2 = (half ^ (t >> 2)) & 1; \
        char* dst = sm + (so) + 24576 + t * 32 + u2 * 16; \
        if (G == 1) { \
            B8 ph, pm, pl; \
            _Pragma("unroll") \
            for (int e = 0; e < 8; e++) { \
                float v = bf[half * 8 + e]; \
                __nv_bfloat16 H = __float2bfloat16(v); \
                float r = v - __bfloat162float(H); \
                __nv_bfloat16 M = __float2bfloat16(r); \
                ph.h[e] = H; pm.h[e] = M; \
                pl.h[e] = __float2bfloat16(r - __bfloat162float(M)); \
            } \
            *(uint4*)(dst) = ph.v; \
            *(uint4*)(dst + 4096) = pm.v; \
            *(uint4*)(dst + 8192) = pl.v; \
        } else { \
            B8 u0, u1; \
            _Pragma("unroll") \
            for (int e = 0; e < 8; e++) { u0.h[e] = bh[half * 8 + e]; u1.h[e] = bl[half * 8 + e]; } \
            *(uint4*)(dst) = u0.v; \
            *(uint4*)(dst + 4096) = u1.v; \
        } \
    } \
} while (0)

    // prologue: chunk 0
    if (t < 128) LOAD_B(0);
    ISSUE_A(0, 0);
    if (t < 128) STORE_B(0);
    asm volatile("cp.async.wait_group 0;");
    __syncthreads();

    for (int c = 0; c < 16; c++) {
        const uint32_t so_cur = (c & 1) * STG;
        const uint32_t so_nxt = ((c + 1) & 1) * STG;
        if (c < 15) {
            ISSUE_A(c + 1, so_nxt);
            if (t < 128) LOAD_B(c + 1);
        }
        // ---- MMA on current stage ----
        {
            uint32_t Ast = sb + so_cur;
            uint32_t Bst = Ast + 24576;
            uint32_t Bf[PB][8][2];
#pragma unroll
            for (int p = 0; p < PB; p++)
#pragma unroll
                for (int nt = 0; nt < 8; nt++) {
                    int row = pix0w + nt * 8 + bRowOff;
                    uint32_t ad = Bst + p * 4096 + row * 32 + (((bUnit ^ (row >> 2)) & 1) << 4);
                    ldmx2(Bf[p][nt][0], Bf[p][nt][1], ad);
                }
#pragma unroll
            for (int mt = 0; mt < 4; mt++) {
#pragma unroll
                for (int pa = 0; pa < PA; pa++) {
                    int row = ch0 + mt * 16 + aRow;
                    uint32_t ad = Ast + pa * 8192 + row * 32 + (((aUnit ^ (row >> 2)) & 1) << 4);
                    uint32_t a[4];
                    ldmx4(a[0], a[1], a[2], a[3], ad);
                    const int nb = (G == 1) ? (3 - pa) : (2 - pa);
#pragma unroll
                    for (int pb = 0; pb < PB; pb++) {
                        if (pb >= nb) break;
#pragma unroll
                        for (int nt = 0; nt < 8; nt++)
                            mma16816(d[mt][nt], a, Bf[pb][nt][0], Bf[pb][nt][1]);
                    }
                }
            }
        }
        if (c < 15) {
            if (t < 128) STORE_B(so_nxt);
            asm volatile("cp.async.wait_group 0;");
        }
        __syncthreads();
    }

    // ---- epilogue ----
    const int rq = lane >> 2, q = lane & 3;
    if (G == 1) {
        float* s_sum = (float*)sm;
        float* s_sq = s_sum + 256;
        s_sum[t] = 0.f; s_sq[t] = 0.f;
        __syncthreads();
#pragma unroll
        for (int mt = 0; mt < 4; mt++) {
            int c_0 = ch0 + mt * 16 + rq, c_1 = c_0 + 8;
            float s0 = 0.f, q0 = 0.f, s1 = 0.f, q1 = 0.f;
#pragma unroll
            for (int nt = 0; nt < 8; nt++) {
                float v0 = d[mt][nt][0], v1 = d[mt][nt][1];
                float v2 = d[mt][nt][2], v3 = d[mt][nt][3];
                size_t PP = (size_t)P0 + pix0w + nt * 8 + q * 2;
                *(float2*)&g_h[(size_t)c_0 * NTOT + PP] = make_float2(v0, v1);
                *(float2*)&g_h[(size_t)c_1 * NTOT + PP] = make_float2(v2, v3);
                s0 += v0 + v1; q0 += v0 * v0 + v1 * v1;
                s1 += v2 + v3; q1 += v2 * v2 + v3 * v3;
            }
#pragma unroll
            for (int o = 1; o <= 2; o <<= 1) {
                s0 += __shfl_xor_sync(0xFFFFFFFFu, s0, o);
                q0 += __shfl_xor_sync(0xFFFFFFFFu, q0, o);
                s1 += __shfl_xor_sync(0xFFFFFFFFu, s1, o);
                q1 += __shfl_xor_sync(0xFFFFFFFFu, q1, o);
            }
            if (q == 0) {
                atomicAdd(&s_sum[c_0], s0); atomicAdd(&s_sq[c_0], q0);
                atomicAdd(&s_sum[c_1], s1); atomicAdd(&s_sq[c_1], q1);
            }
        }
        __syncthreads();
        atomicAdd(&g_sum[t], s_sum[t]);
        atomicAdd(&g_sumsq[t], s_sq[t]);
    } else {
        const size_t obase = (size_t)(P0 >> 14) * CHW + (P0 & 16383);
#pragma unroll
        for (int mt = 0; mt < 4; mt++) {
            int c_0 = ch0 + mt * 16 + rq, c_1 = c_0 + 8;
            float b0 = s_bias[c_0], b1 = s_bias[c_1];
#pragma unroll
            for (int nt = 0; nt < 8; nt++) {
                int pixL = pix0w + nt * 8 + q * 2;
                float f0 = s_fac[pixL], f1 = s_fac[pixL + 1];
                *(float2*)&out[obase + (size_t)c_0 * HW + pixL] =
                    make_float2((d[mt][nt][0] + b0) * f0, (d[mt][nt][1] + b0) * f1);
                *(float2*)&out[obase + (size_t)c_1 * HW + pixL] =
                    make_float2((d[mt][nt][2] + b1) * f0, (d[mt][nt][3] + b1) * f1);
            }
        }
    }
#undef ISSUE_A
#undef LOAD_B
#undef STORE_B
}

// ---------------- BN finalize ----------------
__global__ void k_bnfin(const float* __restrict__ gamma, const float* __restrict__ beta) {
    int c = threadIdx.x;
    float n = (float)NTOT;
    float mu = g_sum[c] / n;
    float var = fmaxf(g_sumsq[c] / n - mu * mu, 0.f);
    float a = gamma[c] * rsqrtf(var + 1e-5f);
    g_bna[c] = a; g_bnb[c] = beta[c] - mu * a;
}

// ---------------- fused: BN+ReLU+split -> g_h2, mean/logvar GEMV, prob_x, u ----------------
__global__ void k_fuse(const float* __restrict__ Wm, const float* __restrict__ Ws,
                       const float* __restrict__ eps1, const float* __restrict__ eps50,
                       float* __restrict__ out) {
    int t = threadIdx.x;
    int P = blockIdx.x * 256 + t;
    float m = 0.f, lv = 0.f;
    for (int ch = 0; ch < Cc; ch++) {
        float v = g_h[(size_t)ch * NTOT + P];
        float r = fmaxf(fmaf(g_bna[ch], v, g_bnb[ch]), 0.f);
        __nv_bfloat16 H = __float2bfloat16(r);
        g_h2hi[(size_t)ch * NTOT + P] = H;
        g_h2lo[(size_t)ch * NTOT + P] = __float2bfloat16(r - __bfloat162float(H));
        m = fmaf(Wm[ch], r, m);
        lv = fmaf(Ws[ch], r, lv);
    }
    float stdv = expf(0.5f * lv);
    out[PROB_OFF + P] = fmaf(eps1[P], stdv, m);
    int b = P >> 14, hw = P & (HW - 1);
    const float* e = eps50 + (size_t)b * NS * HW + hw;
    float v[NS], s = 0.f;
#pragma unroll
    for (int i = 0; i < NS; i++) {
        float tt = fmaf(e[(size_t)i * HW], stdv, m);
        float pv = 1.f / (1.f + expf(-tt));
        v[i] = pv; s += pv;
    }
    float mm = s * (1.f / NS), ss = 0.f;
#pragma unroll
    for (int i = 0; i < NS; i++) { float dd = v[i] - mm; ss = fmaf(dd, dd, ss); }
    g_u[P] = ss * (1.f / (NS - 1));
}

// ---------------- 3x 7x7 box filter + global min/max ----------------
__global__ void k_box() {
    extern __shared__ float smf[];
    float* s0 = smf; float* s1 = smf + HW;
    __shared__ unsigned int smn, smx;
    const int b = blockIdx.x, tid = threadIdx.x, nth = blockDim.x;
    if (tid == 0) { smn = 0xFFFFFFFFu; smx = 0u; }
    for (int i = tid; i < HW; i += nth) s0[i] = g_u[(size_t)b * HW + i];
    __syncthreads();
    for (int it = 0; it < 3; it++) {
        for (int i = tid; i < HW; i += nth) {
            int y = i >> 7, x = i & 127;
            int x0 = x - 3 < 0 ? 0 : x - 3, x1 = x + 3 > 127 ? 127 : x + 3;
            float s = 0.f;
            for (int xx = x0; xx <= x1; xx++) s += s0[(y << 7) + xx];
            s1[i] = s;
        }
        __syncthreads();
        for (int i = tid; i < HW; i += nth) {
            int y = i >> 7, x = i & 127;
            int y0 = y - 3 < 0 ? 0 : y - 3, y1 = y + 3 > 127 ? 127 : y + 3;
            float s = 0.f;
            for (int yy = y0; yy <= y1; yy++) s += s1[(yy << 7) + x];
            s0[i] = s;
        }
        __syncthreads();
    }
    float lmn = 3.4e38f, lmx = -3.4e38f;
    for (int i = tid; i < HW; i += nth) {
        float w = s0[i];
        g_u[(size_t)b * HW + i] = w;
        lmn = fminf(lmn, w); lmx = fmaxf(lmx, w);
    }
    atomicMin(&smn, __float_as_uint(lmn));
    atomicMax(&smx, __float_as_uint(lmx));
    __syncthreads();
    if (tid == 0) { atomicMin(&g_minb, smn); atomicMax(&g_maxb, smx); }
}

// ---------------- launch ----------------
extern "C" void kernel_launch(void* const* d_in, const int* in_sizes, int n_in,
                              void* d_out, int out_size) {
    const float* x     = (const float*)d_in[0];
    const float* Wproj = (const float*)d_in[1];
    const float* gamma = (const float*)d_in[2];
    const float* beta  = (const float*)d_in[3];
    const float* Wconv = (const float*)d_in[4];
    const float* bconv = (const float*)d_in[5];
    const float* Wmean = (const float*)d_in[6];
    const float* Wstd  = (const float*)d_in[7];
    const float* eps1  = (const float*)d_in[8];
    const float* eps50 = (const float*)d_in[9];
    const float* randu = (const float*)d_in[10];
    float* out = (float*)d_out;

    cudaFuncSetAttribute(k_box, cudaFuncAttributeMaxDynamicSharedMemorySize, 2 * HW * 4);
    cudaFuncSetAttribute(k_gemm<1>, cudaFuncAttributeMaxDynamicSharedMemorySize, SMEM_GEMM);
    cudaFuncSetAttribute(k_gemm<2>, cudaFuncAttributeMaxDynamicSharedMemorySize, SMEM_GEMM);

    k_init<<<1, 256>>>();
    k_prep_w<<<512, 256>>>(Wproj, Wconv);
    k_gemm<1><<<NTOT / 128, 256, SMEM_GEMM>>>(x, nullptr, nullptr, nullptr);
    k_bnfin<<<1, 256>>>(gamma, beta);
    k_fuse<<<NTOT / 256, 256>>>(Wmean, Wstd, eps1, eps50, out);
    k_box<<<Bb, 1024, 2 * HW * 4>>>();
    k_gemm<2><<<NTOT / 128, 256, SMEM_GEMM>>>(nullptr, out, bconv, randu);
}

// round 5
// speedup vs baseline: 1.9703x; 1.4035x over previous
#include <cuda_runtime.h>
#include <cuda_fp16.h>
#include <math.h>
#include <stdint.h>

#define Cc 256
#define HW 16384
#define Bb 8
#define CHW (Cc*HW)
#define NTOT (Bb*HW)
#define TOTAL (Bb*CHW)
#define PROB_OFF TOTAL
#define NS 50

#define STG 24576            // bytes per stage: A 16KB (2 parts) + B 8KB (2 parts)
#define FAC_OFF (2*STG)      // 49152
#define BIAS_OFF (FAC_OFF+512)
#define BNA_OFF (BIAS_OFF+1024)
#define BNB_OFF (BNA_OFF+1024)
#define SMEM_GEMM (BNB_OFF+1024)

// ---------------- device globals ----------------
__device__ float g_h[TOTAL];                 // h pre-BN, [ch][P] fp32
__device__ __half g_wA[2*2*Cc*Cc];           // weights: [gemm][part][chunk][4096]
__device__ float g_sum[Cc], g_sumsq[Cc], g_bna[Cc], g_bnb[Cc];
__device__ float g_u[NTOT];
__device__ unsigned int g_minb, g_maxb;

union H8 { __half h[8]; uint4 v; };

__device__ __forceinline__ uint32_t s2u(const void* p) {
    uint32_t a;
    asm("{ .reg .u64 t; cvta.to.shared.u64 t, %1; cvt.u32.u64 %0, t; }" : "=r"(a) : "l"(p));
    return a;
}
__device__ __forceinline__ void cpa16(uint32_t dst, const void* src) {
    asm volatile("cp.async.cg.shared.global [%0], [%1], 16;" :: "r"(dst), "l"(src));
}
__device__ __forceinline__ void ldmx4(uint32_t& a0, uint32_t& a1, uint32_t& a2, uint32_t& a3, uint32_t ad) {
    asm volatile("ldmatrix.sync.aligned.m8n8.x4.shared.b16 {%0,%1,%2,%3}, [%4];"
                 : "=r"(a0), "=r"(a1), "=r"(a2), "=r"(a3) : "r"(ad));
}
__device__ __forceinline__ void ldmx2(uint32_t& b0, uint32_t& b1, uint32_t ad) {
    asm volatile("ldmatrix.sync.aligned.m8n8.x2.shared.b16 {%0,%1}, [%2];"
                 : "=r"(b0), "=r"(b1) : "r"(ad));
}
__device__ __forceinline__ void mma16816(float* d, const uint32_t* a, uint32_t b0, uint32_t b1) {
    asm volatile("mma.sync.aligned.m16n8k16.row.col.f32.f16.f16.f32 "
                 "{%0,%1,%2,%3}, {%4,%5,%6,%7}, {%8,%9}, {%0,%1,%2,%3};"
                 : "+f"(d[0]), "+f"(d[1]), "+f"(d[2]), "+f"(d[3])
                 : "r"(a[0]), "r"(a[1]), "r"(a[2]), "r"(a[3]), "r"(b0), "r"(b1));
}

// ---------------- init ----------------
__global__ void k_init() {
    int t = threadIdx.x;
    if (t < Cc) { g_sum[t] = 0.f; g_sumsq[t] = 0.f; }
    if (t == 0) { g_minb = 0xFFFFFFFFu; g_maxb = 0u; }
}

// ---------------- weight prep: 2-way fp16 split, chunked+swizzled ----------------
__global__ void k_prep_w(const float* __restrict__ Wp, const float* __restrict__ Wc) {
    int idx = blockIdx.x * blockDim.x + threadIdx.x;   // 0..131071
    int g = idx >> 16, ch = (idx >> 8) & 255, k = idx & 255;
    float w = (g ? Wc : Wp)[ch * Cc + k];
    __half H = __float2half_rn(w);
    __half L = __float2half_rn(w - __half2float(H));
    int kc = k >> 4, kk = k & 15;
    int unit = ((kk >> 3) ^ (ch >> 2)) & 1;
    int elem = (ch * 32 + unit * 16 + (kk & 7) * 2) >> 1;
    size_t base = (size_t)((g * 2) * 16 + kc) * 4096 + elem;
    g_wA[base]         = H;
    g_wA[base + 65536] = L;     // part stride = 16 chunks * 4096
}

// ---------------- mma.sync GEMM: tile 256ch x 128pix, K=256 in 16 chunks ----------------
// G=1: B = x fp32 (2-way fp16 split, 4 terms), epilogue -> g_h + BN stats
// G=2: B = relu(bn(g_h)) split inline (3 terms), epilogue -> out with bias + (1-u)*mask
template<int G>
__global__ __launch_bounds__(256, 1)
void k_gemm(const float* __restrict__ x, float* __restrict__ out,
            const float* __restrict__ bconv, const float* __restrict__ randu) {
    extern __shared__ __align__(16) char sm[];
    const uint32_t sb = s2u(sm);
    const int t = threadIdx.x, wid = t >> 5, lane = t & 31;
    const int P0 = blockIdx.x * 128;

    const int ch0 = (wid >> 1) * 64;
    const int pix0w = (wid & 1) * 64;
    const int aRow = lane & 15, aUnit = lane >> 4;
    const int l15 = lane & 15;
    const int bRowOff = l15 & 7, bUnit = (l15 >> 3) & 1;
    const int px = t & 127, kg = t >> 7;       // B loader: pixel + k-half

    float* s_fac  = (float*)(sm + FAC_OFF);
    float* s_bias = (float*)(sm + BIAS_OFF);
    float* s_bna  = (float*)(sm + BNA_OFF);
    float* s_bnb  = (float*)(sm + BNB_OFF);
    if (G == 2) {
        if (t < 128) {
            float mn = __uint_as_float(g_minb), mx = __uint_as_float(g_maxb);
            float un = (g_u[P0 + t] - mn) / (mx - mn);
            s_fac[t] = (1.f - un) * ((un < randu[P0 + t]) ? 1.f : 0.f);
        }
        s_bias[t] = bconv[t];
        s_bna[t] = g_bna[t];
        s_bnb[t] = g_bnb[t];
        __syncthreads();
    }

    float d[4][8][4];
#pragma unroll
    for (int i = 0; i < 4; i++)
#pragma unroll
        for (int j = 0; j < 8; j++)
#pragma unroll
            for (int e = 0; e < 4; e++) d[i][j][e] = 0.f;

    float bf[8];
    const float* xs = (G == 1) ? (x + (size_t)(P0 >> 14) * CHW + (P0 & 16383) + px)
                               : (g_h + P0 + px);

#define ISSUE_A(cc, so) do { \
    _Pragma("unroll") \
    for (int i = 0; i < 4; i++) { \
        int u = t + i * 256; \
        int p = u >> 9, w = u & 511; \
        const char* src = (const char*)g_wA + (size_t)(((G - 1) * 2 + p) * 16 + (cc)) * 8192 + w * 16; \
        cpa16(sb + (so) + p * 8192 + w * 16, src); \
    } \
    asm volatile("cp.async.commit_group;"); \
} while (0)

#define LOAD_B(cc) do { \
    if (G == 1) { \
        _Pragma("unroll") \
        for (int e = 0; e < 8; e++) bf[e] = xs[(size_t)((cc) * 16 + kg * 8 + e) * HW]; \
    } else { \
        _Pragma("unroll") \
        for (int e = 0; e < 8; e++) { \
            int ch = (cc) * 16 + kg * 8 + e; \
            float v = xs[(size_t)ch * NTOT]; \
            bf[e] = fmaxf(fmaf(s_bna[ch], v, s_bnb[ch]), 0.f); \
        } \
    } \
} while (0)

#define STORE_B(so) do { \
    H8 u0, u1; \
    _Pragma("unroll") \
    for (int e = 0; e < 8; e++) { \
        __half H = __float2half_rn(bf[e]); \
        u0.h[e] = H; \
        u1.h[e] = __float2half_rn(bf[e] - __half2float(H)); \
    } \
    int u2 = (kg ^ (px >> 2)) & 1; \
    char* dst = sm + (so) + 16384 + px * 32 + u2 * 16; \
    *(uint4*)(dst) = u0.v; \
    *(uint4*)(dst + 4096) = u1.v; \
} while (0)

    // prologue: chunk 0
    LOAD_B(0);
    ISSUE_A(0, 0);
    STORE_B(0);
    asm volatile("cp.async.wait_group 0;");
    __syncthreads();

    for (int c = 0; c < 16; c++) {
        const uint32_t so_cur = (c & 1) * STG;
        const uint32_t so_nxt = ((c + 1) & 1) * STG;
        if (c < 15) {
            ISSUE_A(c + 1, so_nxt);
            LOAD_B(c + 1);
        }
        // ---- MMA on current stage ----
        {
            uint32_t Ast = sb + so_cur;
            uint32_t Bst = Ast + 16384;
            uint32_t Bf[2][8][2];
#pragma unroll
            for (int p = 0; p < 2; p++)
#pragma unroll
                for (int nt = 0; nt < 8; nt++) {
                    int row = pix0w + nt * 8 + bRowOff;
                    uint32_t ad = Bst + p * 4096 + row * 32 + (((bUnit ^ (row >> 2)) & 1) << 4);
                    ldmx2(Bf[p][nt][0], Bf[p][nt][1], ad);
                }
#pragma unroll
            for (int mt = 0; mt < 4; mt++) {
#pragma unroll
                for (int pa = 0; pa < 2; pa++) {
                    int row = ch0 + mt * 16 + aRow;
                    uint32_t ad = Ast + pa * 8192 + row * 32 + (((aUnit ^ (row >> 2)) & 1) << 4);
                    uint32_t a[4];
                    ldmx4(a[0], a[1], a[2], a[3], ad);
                    const int nb = (G == 1) ? 2 : (2 - pa);
#pragma unroll
                    for (int pb = 0; pb < 2; pb++) {
                        if (pb >= nb) break;
#pragma unroll
                        for (int nt = 0; nt < 8; nt++)
                            mma16816(d[mt][nt], a, Bf[pb][nt][0], Bf[pb][nt][1]);
                    }
                }
            }
        }
        if (c < 15) {
            STORE_B(so_nxt);
            asm volatile("cp.async.wait_group 0;");
        }
        __syncthreads();
    }

    // ---- epilogue ----
    const int rq = lane >> 2, q = lane & 3;
    if (G == 1) {
        float* s_sum = (float*)sm;
        float* s_sq = s_sum + 256;
        s_sum[t] = 0.f; s_sq[t] = 0.f;
        __syncthreads();
#pragma unroll
        for (int mt = 0; mt < 4; mt++) {
            int c_0 = ch0 + mt * 16 + rq, c_1 = c_0 + 8;
            float s0 = 0.f, q0 = 0.f, s1 = 0.f, q1 = 0.f;
#pragma unroll
            for (int nt = 0; nt < 8; nt++) {
                float v0 = d[mt][nt][0], v1 = d[mt][nt][1];
                float v2 = d[mt][nt][2], v3 = d[mt][nt][3];
                size_t PP = (size_t)P0 + pix0w + nt * 8 + q * 2;
                *(float2*)&g_h[(size_t)c_0 * NTOT + PP] = make_float2(v0, v1);
                *(float2*)&g_h[(size_t)c_1 * NTOT + PP] = make_float2(v2, v3);
                s0 += v0 + v1; q0 += v0 * v0 + v1 * v1;
                s1 += v2 + v3; q1 += v2 * v2 + v3 * v3;
            }
#pragma unroll
            for (int o = 1; o <= 2; o <<= 1) {
                s0 += __shfl_xor_sync(0xFFFFFFFFu, s0, o);
                q0 += __shfl_xor_sync(0xFFFFFFFFu, q0, o);
                s1 += __shfl_xor_sync(0xFFFFFFFFu, s1, o);
                q1 += __shfl_xor_sync(0xFFFFFFFFu, q1, o);
            }
            if (q == 0) {
                atomicAdd(&s_sum[c_0], s0); atomicAdd(&s_sq[c_0], q0);
                atomicAdd(&s_sum[c_1], s1); atomicAdd(&s_sq[c_1], q1);
            }
        }
        __syncthreads();
        atomicAdd(&g_sum[t], s_sum[t]);
        atomicAdd(&g_sumsq[t], s_sq[t]);
    } else {
        const size_t obase = (size_t)(P0 >> 14) * CHW + (P0 & 16383);
#pragma unroll
        for (int mt = 0; mt < 4; mt++) {
            int c_0 = ch0 + mt * 16 + rq, c_1 = c_0 + 8;
            float b0 = s_bias[c_0], b1 = s_bias[c_1];
#pragma unroll
            for (int nt = 0; nt < 8; nt++) {
                int pixL = pix0w + nt * 8 + q * 2;
                float f0 = s_fac[pixL], f1 = s_fac[pixL + 1];
                *(float2*)&out[obase + (size_t)c_0 * HW + pixL] =
                    make_float2((d[mt][nt][0] + b0) * f0, (d[mt][nt][1] + b0) * f1);
                *(float2*)&out[obase + (size_t)c_1 * HW + pixL] =
                    make_float2((d[mt][nt][2] + b1) * f0, (d[mt][nt][3] + b1) * f1);
            }
        }
    }
#undef ISSUE_A
#undef LOAD_B
#undef STORE_B
}

// ---------------- BN finalize ----------------
__global__ void k_bnfin(const float* __restrict__ gamma, const float* __restrict__ beta) {
    int c = threadIdx.x;
    float n = (float)NTOT;
    float mu = g_sum[c] / n;
    float var = fmaxf(g_sumsq[c] / n - mu * mu, 0.f);
    float a = gamma[c] * rsqrtf(var + 1e-5f);
    g_bna[c] = a; g_bnb[c] = beta[c] - mu * a;
}

// ---------------- fused: mean/logvar GEMV, prob_x, u ----------------
__global__ void k_fuse(const float* __restrict__ Wm, const float* __restrict__ Ws,
                       const float* __restrict__ eps1, const float* __restrict__ eps50,
                       float* __restrict__ out) {
    __shared__ float s_a[Cc], s_b[Cc], s_wm[Cc], s_ws[Cc];
    int t = threadIdx.x;
    s_a[t] = g_bna[t]; s_b[t] = g_bnb[t]; s_wm[t] = Wm[t]; s_ws[t] = Ws[t];
    __syncthreads();
    int P = blockIdx.x * 256 + t;
    float m = 0.f, lv = 0.f;
    for (int ch = 0; ch < Cc; ch++) {
        float v = g_h[(size_t)ch * NTOT + P];
        float r = fmaxf(fmaf(s_a[ch], v, s_b[ch]), 0.f);
        m = fmaf(s_wm[ch], r, m);
        lv = fmaf(s_ws[ch], r, lv);
    }
    float stdv = expf(0.5f * lv);
    out[PROB_OFF + P] = fmaf(eps1[P], stdv, m);
    int b = P >> 14, hw = P & (HW - 1);
    const float* e = eps50 + (size_t)b * NS * HW + hw;
    float v[NS], s = 0.f;
#pragma unroll
    for (int i = 0; i < NS; i++) {
        float tt = fmaf(e[(size_t)i * HW], stdv, m);
        float pv = 1.f / (1.f + expf(-tt));
        v[i] = pv; s += pv;
    }
    float mm = s * (1.f / NS), ss = 0.f;
#pragma unroll
    for (int i = 0; i < NS; i++) { float dd = v[i] - mm; ss = fmaf(dd, dd, ss); }
    g_u[P] = ss * (1.f / (NS - 1));
}

// ---------------- 3x 7x7 box filter + global min/max ----------------
__global__ void k_box() {
    extern __shared__ float smf[];
    float* s0 = smf; float* s1 = smf + HW;
    __shared__ unsigned int smn, smx;
    const int b = blockIdx.x, tid = threadIdx.x, nth = blockDim.x;
    if (tid == 0) { smn = 0xFFFFFFFFu; smx = 0u; }
    for (int i = tid; i < HW; i += nth) s0[i] = g_u[(size_t)b * HW + i];
    __syncthreads();
    for (int it = 0; it < 3; it++) {
        for (int i = tid; i < HW; i += nth) {
            int y = i >> 7, x = i & 127;
            int x0 = x - 3 < 0 ? 0 : x - 3, x1 = x + 3 > 127 ? 127 : x + 3;
            float s = 0.f;
            for (int xx = x0; xx <= x1; xx++) s += s0[(y << 7) + xx];
            s1[i] = s;
        }
        __syncthreads();
        for (int i = tid; i < HW; i += nth) {
            int y = i >> 7, x = i & 127;
            int y0 = y - 3 < 0 ? 0 : y - 3, y1 = y + 3 > 127 ? 127 : y + 3;
            float s = 0.f;
            for (int yy = y0; yy <= y1; yy++) s += s1[(yy << 7) + x];
            s0[i] = s;
        }
        __syncthreads();
    }
    float lmn = 3.4e38f, lmx = -3.4e38f;
    for (int i = tid; i < HW; i += nth) {
        float w = s0[i];
        g_u[(size_t)b * HW + i] = w;
        lmn = fminf(lmn, w); lmx = fmaxf(lmx, w);
    }
    atomicMin(&smn, __float_as_uint(lmn));
    atomicMax(&smx, __float_as_uint(lmx));
    __syncthreads();
    if (tid == 0) { atomicMin(&g_minb, smn); atomicMax(&g_maxb, smx); }
}

// ---------------- launch ----------------
extern "C" void kernel_launch(void* const* d_in, const int* in_sizes, int n_in,
                              void* d_out, int out_size) {
    const float* x     = (const float*)d_in[0];
    const float* Wproj = (const float*)d_in[1];
    const float* gamma = (const float*)d_in[2];
    const float* beta  = (const float*)d_in[3];
    const float* Wconv = (const float*)d_in[4];
    const float* bconv = (const float*)d_in[5];
    const float* Wmean = (const float*)d_in[6];
    const float* Wstd  = (const float*)d_in[7];
    const float* eps1  = (const float*)d_in[8];
    const float* eps50 = (const float*)d_in[9];
    const float* randu = (const float*)d_in[10];
    float* out = (float*)d_out;

    cudaFuncSetAttribute(k_box, cudaFuncAttributeMaxDynamicSharedMemorySize, 2 * HW * 4);
    cudaFuncSetAttribute(k_gemm<1>, cudaFuncAttributeMaxDynamicSharedMemorySize, SMEM_GEMM);
    cudaFuncSetAttribute(k_gemm<2>, cudaFuncAttributeMaxDynamicSharedMemorySize, SMEM_GEMM);

    k_init<<<1, 256>>>();
    k_prep_w<<<512, 256>>>(Wproj, Wconv);
    k_gemm<1><<<NTOT / 128, 256, SMEM_GEMM>>>(x, nullptr, nullptr, nullptr);
    k_bnfin<<<1, 256>>>(gamma, beta);
    k_fuse<<<NTOT / 256, 256>>>(Wmean, Wstd, eps1, eps50, out);
    k_box<<<Bb, 1024, 2 * HW * 4>>>();
    k_gemm<2><<<NTOT / 128, 256, SMEM_GEMM>>>(nullptr, out, bconv, randu);
}

// round 6
// speedup vs baseline: 2.3476x; 1.1915x over previous
#include <cuda_runtime.h>
#include <cuda_fp16.h>
#include <math.h>
#include <stdint.h>

#define Cc 256
#define HW 16384
#define Bb 8
#define CHW (Cc*HW)
#define NTOT (Bb*HW)
#define TOTAL (Bb*CHW)
#define PROB_OFF TOTAL
#define NS 50

#define STG 24576            // bytes per stage: A 16KB (2 parts) + B 8KB (2 parts)
#define FAC_OFF (2*STG)      // 49152
#define BIAS_OFF (FAC_OFF+512)
#define BNA_OFF (BIAS_OFF+1024)
#define BNB_OFF (BNA_OFF+1024)
#define SMEM_GEMM (BNB_OFF+1024)

// ---------------- device globals ----------------
__device__ float g_h[TOTAL];                 // h pre-BN, [ch][P] fp32
__device__ __half g_wA[2*2*Cc*Cc];           // weights: [gemm][part][chunk][4096]
__device__ float g_sum[Cc], g_sumsq[Cc], g_bna[Cc], g_bnb[Cc];
__device__ float g_u[NTOT];
__device__ unsigned int g_minb, g_maxb;

union H8 { __half h[8]; uint4 v; };

__device__ __forceinline__ uint32_t s2u(const void* p) {
    uint32_t a;
    asm("{ .reg .u64 t; cvta.to.shared.u64 t, %1; cvt.u32.u64 %0, t; }" : "=r"(a) : "l"(p));
    return a;
}
__device__ __forceinline__ void cpa16(uint32_t dst, const void* src) {
    asm volatile("cp.async.cg.shared.global [%0], [%1], 16;" :: "r"(dst), "l"(src));
}
__device__ __forceinline__ void ldmx4(uint32_t& a0, uint32_t& a1, uint32_t& a2, uint32_t& a3, uint32_t ad) {
    asm volatile("ldmatrix.sync.aligned.m8n8.x4.shared.b16 {%0,%1,%2,%3}, [%4];"
                 : "=r"(a0), "=r"(a1), "=r"(a2), "=r"(a3) : "r"(ad));
}
__device__ __forceinline__ void ldmx2(uint32_t& b0, uint32_t& b1, uint32_t ad) {
    asm volatile("ldmatrix.sync.aligned.m8n8.x2.shared.b16 {%0,%1}, [%2];"
                 : "=r"(b0), "=r"(b1) : "r"(ad));
}
__device__ __forceinline__ void mma16816(float* d, const uint32_t* a, uint32_t b0, uint32_t b1) {
    asm volatile("mma.sync.aligned.m16n8k16.row.col.f32.f16.f16.f32 "
                 "{%0,%1,%2,%3}, {%4,%5,%6,%7}, {%8,%9}, {%0,%1,%2,%3};"
                 : "+f"(d[0]), "+f"(d[1]), "+f"(d[2]), "+f"(d[3])
                 : "r"(a[0]), "r"(a[1]), "r"(a[2]), "r"(a[3]), "r"(b0), "r"(b1));
}

// ---------------- init ----------------
__global__ void k_init() {
    int t = threadIdx.x;
    if (t < Cc) { g_sum[t] = 0.f; g_sumsq[t] = 0.f; }
    if (t == 0) { g_minb = 0xFFFFFFFFu; g_maxb = 0u; }
}

// ---------------- weight prep: 2-way fp16 split, chunked+swizzled ----------------
__global__ void k_prep_w(const float* __restrict__ Wp, const float* __restrict__ Wc) {
    int idx = blockIdx.x * blockDim.x + threadIdx.x;   // 0..131071
    int g = idx >> 16, ch = (idx >> 8) & 255, k = idx & 255;
    float w = (g ? Wc : Wp)[ch * Cc + k];
    __half H = __float2half_rn(w);
    __half L = __float2half_rn(w - __half2float(H));
    int kc = k >> 4, kk = k & 15;
    int unit = ((kk >> 3) ^ (ch >> 2)) & 1;
    int elem = (ch * 32 + unit * 16 + (kk & 7) * 2) >> 1;
    size_t base = (size_t)((g * 2) * 16 + kc) * 4096 + elem;
    g_wA[base]         = H;
    g_wA[base + 65536] = L;     // part stride = 16 chunks * 4096
}

// ---------------- mma.sync GEMM: tile 256ch x 128pix, K=256 in 16 chunks ----------------
// G=1: B = x fp32 (2-way fp16 split, 3 terms), epilogue -> g_h + BN stats
// G=2: B = relu(bn(g_h)) split inline (3 terms), epilogue -> out with bias + (1-u)*mask
template<int G>
__global__ __launch_bounds__(256, 1)
void k_gemm(const float* __restrict__ x, float* __restrict__ out,
            const float* __restrict__ bconv, const float* __restrict__ randu) {
    extern __shared__ __align__(16) char sm[];
    const uint32_t sb = s2u(sm);
    const int t = threadIdx.x, wid = t >> 5, lane = t & 31;
    const int P0 = blockIdx.x * 128;

    const int ch0 = (wid >> 1) * 64;
    const int pix0w = (wid & 1) * 64;
    const int aRow = lane & 15, aUnit = lane >> 4;
    const int l15 = lane & 15;
    const int bRowOff = l15 & 7, bUnit = (l15 >> 3) & 1;
    const int px = t & 127, kg = t >> 7;       // B loader: pixel + k-half

    float* s_fac  = (float*)(sm + FAC_OFF);
    float* s_bias = (float*)(sm + BIAS_OFF);
    float* s_bna  = (float*)(sm + BNA_OFF);
    float* s_bnb  = (float*)(sm + BNB_OFF);
    if (G == 2) {
        if (t < 128) {
            float mn = __uint_as_float(g_minb), mx = __uint_as_float(g_maxb);
            float un = (g_u[P0 + t] - mn) / (mx - mn);
            s_fac[t] = (1.f - un) * ((un < randu[P0 + t]) ? 1.f : 0.f);
        }
        s_bias[t] = bconv[t];
        s_bna[t] = g_bna[t];
        s_bnb[t] = g_bnb[t];
        __syncthreads();
    }

    float d[4][8][4];
#pragma unroll
    for (int i = 0; i < 4; i++)
#pragma unroll
        for (int j = 0; j < 8; j++)
#pragma unroll
            for (int e = 0; e < 4; e++) d[i][j][e] = 0.f;

    float bf[8];
    const float* xs = (G == 1) ? (x + (size_t)(P0 >> 14) * CHW + (P0 & 16383) + px)
                               : (g_h + P0 + px);

#define ISSUE_A(cc, so) do { \
    _Pragma("unroll") \
    for (int i = 0; i < 4; i++) { \
        int u = t + i * 256; \
        int p = u >> 9, w = u & 511; \
        const char* src = (const char*)g_wA + (size_t)(((G - 1) * 2 + p) * 16 + (cc)) * 8192 + w * 16; \
        cpa16(sb + (so) + p * 8192 + w * 16, src); \
    } \
    asm volatile("cp.async.commit_group;"); \
} while (0)

#define LOAD_B(cc) do { \
    if (G == 1) { \
        _Pragma("unroll") \
        for (int e = 0; e < 8; e++) bf[e] = xs[(size_t)((cc) * 16 + kg * 8 + e) * HW]; \
    } else { \
        _Pragma("unroll") \
        for (int e = 0; e < 8; e++) { \
            int ch = (cc) * 16 + kg * 8 + e; \
            float v = xs[(size_t)ch * NTOT]; \
            bf[e] = fmaxf(fmaf(s_bna[ch], v, s_bnb[ch]), 0.f); \
        } \
    } \
} while (0)

#define STORE_B(so) do { \
    H8 u0, u1; \
    _Pragma("unroll") \
    for (int e = 0; e < 8; e++) { \
        __half H = __float2half_rn(bf[e]); \
        u0.h[e] = H; \
        u1.h[e] = __float2half_rn(bf[e] - __half2float(H)); \
    } \
    int u2 = (kg ^ (px >> 2)) & 1; \
    char* dst = sm + (so) + 16384 + px * 32 + u2 * 16; \
    *(uint4*)(dst) = u0.v; \
    *(uint4*)(dst + 4096) = u1.v; \
} while (0)

    // prologue: chunk 0
    LOAD_B(0);
    ISSUE_A(0, 0);
    STORE_B(0);
    asm volatile("cp.async.wait_group 0;");
    __syncthreads();

    for (int c = 0; c < 16; c++) {
        const uint32_t so_cur = (c & 1) * STG;
        const uint32_t so_nxt = ((c + 1) & 1) * STG;
        if (c < 15) {
            ISSUE_A(c + 1, so_nxt);
            LOAD_B(c + 1);
        }
        // ---- MMA on current stage: 3 terms (skip Al*Bl) ----
        {
            uint32_t Ast = sb + so_cur;
            uint32_t Bst = Ast + 16384;
            uint32_t Bf[2][8][2];
#pragma unroll
            for (int p = 0; p < 2; p++)
#pragma unroll
                for (int nt = 0; nt < 8; nt++) {
                    int row = pix0w + nt * 8 + bRowOff;
                    uint32_t ad = Bst + p * 4096 + row * 32 + (((bUnit ^ (row >> 2)) & 1) << 4);
                    ldmx2(Bf[p][nt][0], Bf[p][nt][1], ad);
                }
#pragma unroll
            for (int mt = 0; mt < 4; mt++) {
#pragma unroll
                for (int pa = 0; pa < 2; pa++) {
                    int row = ch0 + mt * 16 + aRow;
                    uint32_t ad = Ast + pa * 8192 + row * 32 + (((aUnit ^ (row >> 2)) & 1) << 4);
                    uint32_t a[4];
                    ldmx4(a[0], a[1], a[2], a[3], ad);
                    const int nb = 2 - pa;      // 3 cross terms total
#pragma unroll
                    for (int pb = 0; pb < 2; pb++) {
                        if (pb >= nb) break;
#pragma unroll
                        for (int nt = 0; nt < 8; nt++)
                            mma16816(d[mt][nt], a, Bf[pb][nt][0], Bf[pb][nt][1]);
                    }
                }
            }
        }
        if (c < 15) {
            STORE_B(so_nxt);
            asm volatile("cp.async.wait_group 0;");
        }
        __syncthreads();
    }

    // ---- epilogue ----
    const int rq = lane >> 2, q = lane & 3;
    if (G == 1) {
        float* s_sum = (float*)sm;
        float* s_sq = s_sum + 256;
        s_sum[t] = 0.f; s_sq[t] = 0.f;
        __syncthreads();
#pragma unroll
        for (int mt = 0; mt < 4; mt++) {
            int c_0 = ch0 + mt * 16 + rq, c_1 = c_0 + 8;
            float s0 = 0.f, q0 = 0.f, s1 = 0.f, q1 = 0.f;
#pragma unroll
            for (int nt = 0; nt < 8; nt++) {
                float v0 = d[mt][nt][0], v1 = d[mt][nt][1];
                float v2 = d[mt][nt][2], v3 = d[mt][nt][3];
                size_t PP = (size_t)P0 + pix0w + nt * 8 + q * 2;
                *(float2*)&g_h[(size_t)c_0 * NTOT + PP] = make_float2(v0, v1);
                *(float2*)&g_h[(size_t)c_1 * NTOT + PP] = make_float2(v2, v3);
                s0 += v0 + v1; q0 += v0 * v0 + v1 * v1;
                s1 += v2 + v3; q1 += v2 * v2 + v3 * v3;
            }
#pragma unroll
            for (int o = 1; o <= 2; o <<= 1) {
                s0 += __shfl_xor_sync(0xFFFFFFFFu, s0, o);
                q0 += __shfl_xor_sync(0xFFFFFFFFu, q0, o);
                s1 += __shfl_xor_sync(0xFFFFFFFFu, s1, o);
                q1 += __shfl_xor_sync(0xFFFFFFFFu, q1, o);
            }
            if (q == 0) {
                atomicAdd(&s_sum[c_0], s0); atomicAdd(&s_sq[c_0], q0);
                atomicAdd(&s_sum[c_1], s1); atomicAdd(&s_sq[c_1], q1);
            }
        }
        __syncthreads();
        atomicAdd(&g_sum[t], s_sum[t]);
        atomicAdd(&g_sumsq[t], s_sq[t]);
    } else {
        const size_t obase = (size_t)(P0 >> 14) * CHW + (P0 & 16383);
#pragma unroll
        for (int mt = 0; mt < 4; mt++) {
            int c_0 = ch0 + mt * 16 + rq, c_1 = c_0 + 8;
            float b0 = s_bias[c_0], b1 = s_bias[c_1];
#pragma unroll
            for (int nt = 0; nt < 8; nt++) {
                int pixL = pix0w + nt * 8 + q * 2;
                float f0 = s_fac[pixL], f1 = s_fac[pixL + 1];
                *(float2*)&out[obase + (size_t)c_0 * HW + pixL] =
                    make_float2((d[mt][nt][0] + b0) * f0, (d[mt][nt][1] + b0) * f1);
                *(float2*)&out[obase + (size_t)c_1 * HW + pixL] =
                    make_float2((d[mt][nt][2] + b1) * f0, (d[mt][nt][3] + b1) * f1);
            }
        }
    }
#undef ISSUE_A
#undef LOAD_B
#undef STORE_B
}

// ---------------- BN finalize ----------------
__global__ void k_bnfin(const float* __restrict__ gamma, const float* __restrict__ beta) {
    int c = threadIdx.x;
    float n = (float)NTOT;
    float mu = g_sum[c] / n;
    float var = fmaxf(g_sumsq[c] / n - mu * mu, 0.f);
    float a = gamma[c] * rsqrtf(var + 1e-5f);
    g_bna[c] = a; g_bnb[c] = beta[c] - mu * a;
}

// ---------------- fused: mean/logvar GEMV, prob_x, u (fast MUFU path) ----------------
__global__ void k_fuse(const float* __restrict__ Wm, const float* __restrict__ Ws,
                       const float* __restrict__ eps1, const float* __restrict__ eps50,
                       float* __restrict__ out) {
    __shared__ float s_a[Cc], s_b[Cc], s_wm[Cc], s_ws[Cc];
    int t = threadIdx.x;
    s_a[t] = g_bna[t]; s_b[t] = g_bnb[t]; s_wm[t] = Wm[t]; s_ws[t] = Ws[t];
    __syncthreads();
    int P = blockIdx.x * 256 + t;
    float m = 0.f, lv = 0.f;
#pragma unroll 8
    for (int ch = 0; ch < Cc; ch++) {
        float v = g_h[(size_t)ch * NTOT + P];
        float r = fmaxf(fmaf(s_a[ch], v, s_b[ch]), 0.f);
        m = fmaf(s_wm[ch], r, m);
        lv = fmaf(s_ws[ch], r, lv);
    }
    float stdv = __expf(0.5f * lv);
    out[PROB_OFF + P] = fmaf(eps1[P], stdv, m);
    int b = P >> 14, hw = P & (HW - 1);
    const float* e = eps50 + (size_t)b * NS * HW + hw;
    float v[NS], s = 0.f;
#pragma unroll
    for (int i = 0; i < NS; i++) {
        float tt = fmaf(e[(size_t)i * HW], stdv, m);
        float pv = __fdividef(1.f, 1.f + __expf(-tt));
        v[i] = pv; s += pv;
    }
    float mm = s * (1.f / NS), ss = 0.f;
#pragma unroll
    for (int i = 0; i < NS; i++) { float dd = v[i] - mm; ss = fmaf(dd, dd, ss); }
    g_u[P] = ss * (1.f / (NS - 1));
}

// ---------------- 3x 7x7 box filter + global min/max ----------------
__global__ void k_box() {
    extern __shared__ float smf[];
    float* s0 = smf; float* s1 = smf + HW;
    __shared__ unsigned int smn, smx;
    const int b = blockIdx.x, tid = threadIdx.x, nth = blockDim.x;
    if (tid == 0) { smn = 0xFFFFFFFFu; smx = 0u; }
    for (int i = tid; i < HW; i += nth) s0[i] = g_u[(size_t)b * HW + i];
    __syncthreads();
    for (int it = 0; it < 3; it++) {
        for (int i = tid; i < HW; i += nth) {
            int y = i >> 7, x = i & 127;
            int x0 = x - 3 < 0 ? 0 : x - 3, x1 = x + 3 > 127 ? 127 : x + 3;
            float s = 0.f;
            for (int xx = x0; xx <= x1; xx++) s += s0[(y << 7) + xx];
            s1[i] = s;
        }
        __syncthreads();
        for (int i = tid; i < HW; i += nth) {
            int y = i >> 7, x = i & 127;
            int y0 = y - 3 < 0 ? 0 : y - 3, y1 = y + 3 > 127 ? 127 : y + 3;
            float s = 0.f;
            for (int yy = y0; yy <= y1; yy++) s += s1[(yy << 7) + x];
            s0[i] = s;
        }
        __syncthreads();
    }
    float lmn = 3.4e38f, lmx = -3.4e38f;
    for (int i = tid; i < HW; i += nth) {
        float w = s0[i];
        g_u[(size_t)b * HW + i] = w;
        lmn = fminf(lmn, w); lmx = fmaxf(lmx, w);
    }
    atomicMin(&smn, __float_as_uint(lmn));
    atomicMax(&smx, __float_as_uint(lmx));
    __syncthreads();
    if (tid == 0) { atomicMin(&g_minb, smn); atomicMax(&g_maxb, smx); }
}

// ---------------- launch ----------------
extern "C" void kernel_launch(void* const* d_in, const int* in_sizes, int n_in,
                              void* d_out, int out_size) {
    const float* x     = (const float*)d_in[0];
    const float* Wproj = (const float*)d_in[1];
    const float* gamma = (const float*)d_in[2];
    const float* beta  = (const float*)d_in[3];
    const float* Wconv = (const float*)d_in[4];
    const float* bconv = (const float*)d_in[5];
    const float* Wmean = (const float*)d_in[6];
    const float* Wstd  = (const float*)d_in[7];
    const float* eps1  = (const float*)d_in[8];
    const float* eps50 = (const float*)d_in[9];
    const float* randu = (const float*)d_in[10];
    float* out = (float*)d_out;

    cudaFuncSetAttribute(k_box, cudaFuncAttributeMaxDynamicSharedMemorySize, 2 * HW * 4);
    cudaFuncSetAttribute(k_gemm<1>, cudaFuncAttributeMaxDynamicSharedMemorySize, SMEM_GEMM);
    cudaFuncSetAttribute(k_gemm<2>, cudaFuncAttributeMaxDynamicSharedMemorySize, SMEM_GEMM);

    k_init<<<1, 256>>>();
    k_prep_w<<<512, 256>>>(Wproj, Wconv);
    k_gemm<1><<<NTOT / 128, 256, SMEM_GEMM>>>(x, nullptr, nullptr, nullptr);
    k_bnfin<<<1, 256>>>(gamma, beta);
    k_fuse<<<NTOT / 256, 256>>>(Wmean, Wstd, eps1, eps50, out);
    k_box<<<Bb, 1024, 2 * HW * 4>>>();
    k_gemm<2><<<NTOT / 128, 256, SMEM_GEMM>>>(nullptr, out, bconv, randu);
}

// round 8
// speedup vs baseline: 2.6341x; 1.1220x over previous
#include <cuda_runtime.h>
#include <cuda_fp16.h>
#include <math.h>
#include <stdint.h>

#define Cc 256
#define HW 16384
#define Bb 8
#define CHW (Cc*HW)
#define NTOT (Bb*HW)
#define TOTAL (Bb*CHW)
#define PROB_OFF TOTAL
#define NS 50

#define STG 24576            // bytes per stage: A 16KB (2 parts) + B 8KB (2 parts; G2 uses 4KB)
#define FAC_OFF (2*STG)      // 49152
#define BIAS_OFF (FAC_OFF+512)
#define BNA_OFF (BIAS_OFF+1024)
#define BNB_OFF (BNA_OFF+1024)
#define SMEM_GEMM (BNB_OFF+1024)

// ---------------- device globals ----------------
__device__ float g_h[TOTAL];                 // h pre-BN, [ch][P] fp32
__device__ __half g_wA[2*2*Cc*Cc];           // weights: [gemm][part][chunk][4096]
__device__ float g_sum[Cc], g_sumsq[Cc], g_bna[Cc], g_bnb[Cc];
__device__ float g_u[NTOT], g_u2[NTOT];
__device__ unsigned int g_minb, g_maxb;

union H8 { __half h[8]; uint4 v; };

__device__ __forceinline__ uint32_t s2u(const void* p) {
    uint32_t a;
    asm("{ .reg .u64 t; cvta.to.shared.u64 t, %1; cvt.u32.u64 %0, t; }" : "=r"(a) : "l"(p));
    return a;
}
__device__ __forceinline__ void cpa16(uint32_t dst, const void* src) {
    asm volatile("cp.async.cg.shared.global [%0], [%1], 16;" :: "r"(dst), "l"(src));
}
__device__ __forceinline__ void ldmx4(uint32_t& a0, uint32_t& a1, uint32_t& a2, uint32_t& a3, uint32_t ad) {
    asm volatile("ldmatrix.sync.aligned.m8n8.x4.shared.b16 {%0,%1,%2,%3}, [%4];"
                 : "=r"(a0), "=r"(a1), "=r"(a2), "=r"(a3) : "r"(ad));
}
__device__ __forceinline__ void ldmx2(uint32_t& b0, uint32_t& b1, uint32_t ad) {
    asm volatile("ldmatrix.sync.aligned.m8n8.x2.shared.b16 {%0,%1}, [%2];"
                 : "=r"(b0), "=r"(b1) : "r"(ad));
}
__device__ __forceinline__ void mma16816(float* d, const uint32_t* a, uint32_t b0, uint32_t b1) {
    asm volatile("mma.sync.aligned.m16n8k16.row.col.f32.f16.f16.f32 "
                 "{%0,%1,%2,%3}, {%4,%5,%6,%7}, {%8,%9}, {%0,%1,%2,%3};"
                 : "+f"(d[0]), "+f"(d[1]), "+f"(d[2]), "+f"(d[3])
                 : "r"(a[0]), "r"(a[1]), "r"(a[2]), "r"(a[3]), "r"(b0), "r"(b1));
}

// ---------------- init ----------------
__global__ void k_init() {
    int t = threadIdx.x;
    if (t < Cc) { g_sum[t] = 0.f; g_sumsq[t] = 0.f; }
    if (t == 0) { g_minb = 0xFFFFFFFFu; g_maxb = 0u; }
}

// ---------------- weight prep: 2-way fp16 split, chunked+swizzled ----------------
__global__ void k_prep_w(const float* __restrict__ Wp, const float* __restrict__ Wc) {
    int idx = blockIdx.x * blockDim.x + threadIdx.x;   // 0..131071
    int g = idx >> 16, ch = (idx >> 8) & 255, k = idx & 255;
    float w = (g ? Wc : Wp)[ch * Cc + k];
    __half H = __float2half_rn(w);
    __half L = __float2half_rn(w - __half2float(H));
    int kc = k >> 4, kk = k & 15;
    int unit = ((kk >> 3) ^ (ch >> 2)) & 1;
    int elem = (ch * 32 + unit * 16 + (kk & 7) * 2) >> 1;
    size_t base = (size_t)((g * 2) * 16 + kc) * 4096 + elem;
    g_wA[base]         = H;
    g_wA[base + 65536] = L;     // part stride = 16 chunks * 4096
}

// ---------------- mma.sync GEMM: tile 256ch x 128pix, K=256 in 16 chunks ----------------
// G=1: B = x fp32 (2-way fp16 split, 3 terms), epilogue -> g_h + BN stats
// G=2: B = relu(bn(g_h)) fp16 (2 terms: AhBh+AlBh), epilogue -> out with bias + (1-u)*mask
template<int G>
__global__ __launch_bounds__(256, 1)
void k_gemm(const float* __restrict__ x, float* __restrict__ out,
            const float* __restrict__ bconv, const float* __restrict__ randu) {
    extern __shared__ __align__(16) char sm[];
    const uint32_t sb = s2u(sm);
    const int t = threadIdx.x, wid = t >> 5, lane = t & 31;
    const int P0 = blockIdx.x * 128;

    const int ch0 = (wid >> 1) * 64;
    const int pix0w = (wid & 1) * 64;
    const int aRow = lane & 15, aUnit = lane >> 4;
    const int l15 = lane & 15;
    const int bRowOff = l15 & 7, bUnit = (l15 >> 3) & 1;
    const int px = t & 127, kg = t >> 7;       // B loader: pixel + k-half

    float* s_fac  = (float*)(sm + FAC_OFF);
    float* s_bias = (float*)(sm + BIAS_OFF);
    float* s_bna  = (float*)(sm + BNA_OFF);
    float* s_bnb  = (float*)(sm + BNB_OFF);
    if (G == 2) {
        if (t < 128) {
            float mn = __uint_as_float(g_minb), mx = __uint_as_float(g_maxb);
            float un = (g_u2[P0 + t] - mn) / (mx - mn);
            s_fac[t] = (1.f - un) * ((un < randu[P0 + t]) ? 1.f : 0.f);
        }
        s_bias[t] = bconv[t];
        s_bna[t] = g_bna[t];
        s_bnb[t] = g_bnb[t];
        __syncthreads();
    }

    float d[4][8][4];
#pragma unroll
    for (int i = 0; i < 4; i++)
#pragma unroll
        for (int j = 0; j < 8; j++)
#pragma unroll
            for (int e = 0; e < 4; e++) d[i][j][e] = 0.f;

    float bf[8];
    const float* xs = (G == 1) ? (x + (size_t)(P0 >> 14) * CHW + (P0 & 16383) + px)
                               : (g_h + P0 + px);

#define ISSUE_A(cc, so) do { \
    _Pragma("unroll") \
    for (int i = 0; i < 4; i++) { \
        int u = t + i * 256; \
        int p = u >> 9, w = u & 511; \
        const char* src = (const char*)g_wA + (size_t)(((G - 1) * 2 + p) * 16 + (cc)) * 8192 + w * 16; \
        cpa16(sb + (so) + p * 8192 + w * 16, src); \
    } \
    asm volatile("cp.async.commit_group;"); \
} while (0)

#define LOAD_B(cc) do { \
    if (G == 1) { \
        _Pragma("unroll") \
        for (int e = 0; e < 8; e++) bf[e] = xs[(size_t)((cc) * 16 + kg * 8 + e) * HW]; \
    } else { \
        _Pragma("unroll") \
        for (int e = 0; e < 8; e++) { \
            int ch = (cc) * 16 + kg * 8 + e; \
            float v = xs[(size_t)ch * NTOT]; \
            bf[e] = fmaxf(fmaf(s_bna[ch], v, s_bnb[ch]), 0.f); \
        } \
    } \
} while (0)

#define STORE_B(so) do { \
    H8 u0; \
    _Pragma("unroll") \
    for (int e = 0; e < 8; e++) u0.h[e] = __float2half_rn(bf[e]); \
    int u2 = (kg ^ (px >> 2)) & 1; \
    char* dst = sm + (so) + 16384 + px * 32 + u2 * 16; \
    *(uint4*)(dst) = u0.v; \
    if (G == 1) { \
        H8 u1; \
        _Pragma("unroll") \
        for (int e = 0; e < 8; e++) \
            u1.h[e] = __float2half_rn(bf[e] - __half2float(u0.h[e])); \
        *(uint4*)(dst + 4096) = u1.v; \
    } \
} while (0)

    // prologue: chunk 0
    LOAD_B(0);
    ISSUE_A(0, 0);
    STORE_B(0);
    asm volatile("cp.async.wait_group 0;");
    __syncthreads();

    for (int c = 0; c < 16; c++) {
        const uint32_t so_cur = (c & 1) * STG;
        const uint32_t so_nxt = ((c + 1) & 1) * STG;
        if (c < 15) {
            ISSUE_A(c + 1, so_nxt);
            LOAD_B(c + 1);
        }
        // ---- MMA on current stage ----
        {
            uint32_t Ast = sb + so_cur;
            uint32_t Bst = Ast + 16384;
            constexpr int NPB = (G == 1) ? 2 : 1;
            uint32_t Bf[NPB][8][2];
#pragma unroll
            for (int p = 0; p < NPB; p++)
#pragma unroll
                for (int nt = 0; nt < 8; nt++) {
                    int row = pix0w + nt * 8 + bRowOff;
                    uint32_t ad = Bst + p * 4096 + row * 32 + (((bUnit ^ (row >> 2)) & 1) << 4);
                    ldmx2(Bf[p][nt][0], Bf[p][nt][1], ad);
                }
#pragma unroll
            for (int mt = 0; mt < 4; mt++) {
#pragma unroll
                for (int pa = 0; pa < 2; pa++) {
                    int row = ch0 + mt * 16 + aRow;
                    uint32_t ad = Ast + pa * 8192 + row * 32 + (((aUnit ^ (row >> 2)) & 1) << 4);
                    uint32_t a[4];
                    ldmx4(a[0], a[1], a[2], a[3], ad);
                    const int nb = (G == 1) ? (2 - pa) : 1;   // G1: AhBh,AhBl,AlBh  G2: AhBh,AlBh
#pragma unroll
                    for (int pb = 0; pb < NPB; pb++) {
                        if (pb >= nb) break;
#pragma unroll
                        for (int nt = 0; nt < 8; nt++)
                            mma16816(d[mt][nt], a, Bf[pb][nt][0], Bf[pb][nt][1]);
                    }
                }
            }
        }
        if (c < 15) {
            STORE_B(so_nxt);
            asm volatile("cp.async.wait_group 0;");
        }
        __syncthreads();
    }

    // ---- epilogue ----
    const int rq = lane >> 2, q = lane & 3;
    if (G == 1) {
        float* s_sum = (float*)sm;
        float* s_sq = s_sum + 256;
        s_sum[t] = 0.f; s_sq[t] = 0.f;
        __syncthreads();
#pragma unroll
        for (int mt = 0; mt < 4; mt++) {
            int c_0 = ch0 + mt * 16 + rq, c_1 = c_0 + 8;
            float s0 = 0.f, q0 = 0.f, s1 = 0.f, q1 = 0.f;
#pragma unroll
            for (int nt = 0; nt < 8; nt++) {
                float v0 = d[mt][nt][0], v1 = d[mt][nt][1];
                float v2 = d[mt][nt][2], v3 = d[mt][nt][3];
                size_t PP = (size_t)P0 + pix0w + nt * 8 + q * 2;
                *(float2*)&g_h[(size_t)c_0 * NTOT + PP] = make_float2(v0, v1);
                *(float2*)&g_h[(size_t)c_1 * NTOT + PP] = make_float2(v2, v3);
                s0 += v0 + v1; q0 += v0 * v0 + v1 * v1;
                s1 += v2 + v3; q1 += v2 * v2 + v3 * v3;
            }
#pragma unroll
            for (int o = 1; o <= 2; o <<= 1) {
                s0 += __shfl_xor_sync(0xFFFFFFFFu, s0, o);
                q0 += __shfl_xor_sync(0xFFFFFFFFu, q0, o);
                s1 += __shfl_xor_sync(0xFFFFFFFFu, s1, o);
                q1 += __shfl_xor_sync(0xFFFFFFFFu, q1, o);
            }
            if (q == 0) {
                atomicAdd(&s_sum[c_0], s0); atomicAdd(&s_sq[c_0], q0);
                atomicAdd(&s_sum[c_1], s1); atomicAdd(&s_sq[c_1], q1);
            }
        }
        __syncthreads();
        atomicAdd(&g_sum[t], s_sum[t]);
        atomicAdd(&g_sumsq[t], s_sq[t]);
    } else {
        const size_t obase = (size_t)(P0 >> 14) * CHW + (P0 & 16383);
#pragma unroll
        for (int mt = 0; mt < 4; mt++) {
            int c_0 = ch0 + mt * 16 + rq, c_1 = c_0 + 8;
            float b0 = s_bias[c_0], b1 = s_bias[c_1];
#pragma unroll
            for (int nt = 0; nt < 8; nt++) {
                int pixL = pix0w + nt * 8 + q * 2;
                float f0 = s_fac[pixL], f1 = s_fac[pixL + 1];
                *(float2*)&out[obase + (size_t)c_0 * HW + pixL] =
                    make_float2((d[mt][nt][0] + b0) * f0, (d[mt][nt][1] + b0) * f1);
                *(float2*)&out[obase + (size_t)c_1 * HW + pixL] =
                    make_float2((d[mt][nt][2] + b1) * f0, (d[mt][nt][3] + b1) * f1);
            }
        }
    }
#undef ISSUE_A
#undef LOAD_B
#undef STORE_B
}

// ---------------- BN finalize ----------------
__global__ void k_bnfin(const float* __restrict__ gamma, const float* __restrict__ beta) {
    int c = threadIdx.x;
    float n = (float)NTOT;
    float mu = g_sum[c] / n;
    float var = fmaxf(g_sumsq[c] / n - mu * mu, 0.f);
    float a = gamma[c] * rsqrtf(var + 1e-5f);
    g_bna[c] = a; g_bnb[c] = beta[c] - mu * a;
}

// ---------------- fused: mean/logvar GEMV, prob_x, u (fast MUFU path) ----------------
__global__ void k_fuse(const float* __restrict__ Wm, const float* __restrict__ Ws,
                       const float* __restrict__ eps1, const float* __restrict__ eps50,
                       float* __restrict__ out) {
    __shared__ float s_a[Cc], s_b[Cc], s_wm[Cc], s_ws[Cc];
    int t = threadIdx.x;
    s_a[t] = g_bna[t]; s_b[t] = g_bnb[t]; s_wm[t] = Wm[t]; s_ws[t] = Ws[t];
    __syncthreads();
    int P = blockIdx.x * 256 + t;
    float m = 0.f, lv = 0.f;
#pragma unroll 8
    for (int ch = 0; ch < Cc; ch++) {
        float v = g_h[(size_t)ch * NTOT + P];
        float r = fmaxf(fmaf(s_a[ch], v, s_b[ch]), 0.f);
        m = fmaf(s_wm[ch], r, m);
        lv = fmaf(s_ws[ch], r, lv);
    }
    float stdv = __expf(0.5f * lv);
    out[PROB_OFF + P] = fmaf(eps1[P], stdv, m);
    int b = P >> 14, hw = P & (HW - 1);
    const float* e = eps50 + (size_t)b * NS * HW + hw;
    float v[NS], s = 0.f;
#pragma unroll
    for (int i = 0; i < NS; i++) {
        float tt = fmaf(e[(size_t)i * HW], stdv, m);
        float pv = __fdividef(1.f, 1.f + __expf(-tt));
        v[i] = pv; s += pv;
    }
    float mm = s * (1.f / NS), ss = 0.f;
#pragma unroll
    for (int i = 0; i < NS; i++) { float dd = v[i] - mm; ss = fmaf(dd, dd, ss); }
    g_u[P] = ss * (1.f / (NS - 1));
}

// ---------------- 3x 7x7 box filter, banded (64 blocks), + global min/max ----------------
// Per-iteration zero-padding: out-of-image rows are forced to ZERO after each
// vertical pass, so they act as zero padding for the next filter application.
#define BAND 16
#define HALO 9
#define LROWS (BAND + 2*HALO)   // 34
__global__ void k_box() {
    __shared__ float s0[LROWS][128], s1[LROWS][128];
    __shared__ unsigned int smn, smx;
    const int band = blockIdx.x, b = blockIdx.y;
    const int r0 = band * BAND - HALO;     // global row of ly=0
    const int tid = threadIdx.x;
    if (tid == 0) { smn = 0xFFFFFFFFu; smx = 0u; }
    const float* up = g_u + (size_t)b * HW;
    for (int i = tid; i < LROWS * 128; i += 256) {
        int ly = i >> 7, xx = i & 127;
        int gy = r0 + ly;
        s0[ly][xx] = (gy >= 0 && gy < 128) ? up[(gy << 7) + xx] : 0.f;
    }
    __syncthreads();
    int lo = 0, hi = LROWS;
    for (int it = 0; it < 3; it++) {
        for (int i = tid; i < LROWS * 128; i += 256) {
            int ly = i >> 7, xx = i & 127;
            if (ly >= lo && ly < hi) {
                int x0 = xx - 3 < 0 ? 0 : xx - 3;
                int x1 = xx + 3 > 127 ? 127 : xx + 3;
                float s = 0.f;
                for (int x2 = x0; x2 <= x1; x2++) s += s0[ly][x2];
                s1[ly][xx] = s;
            }
        }
        __syncthreads();
        lo += 3; hi -= 3;
        for (int i = tid; i < LROWS * 128; i += 256) {
            int ly = i >> 7, xx = i & 127;
            if (ly >= lo && ly < hi) {
                int gy = r0 + ly;
                float s = 0.f;
#pragma unroll
                for (int yy = -3; yy <= 3; yy++) s += s1[ly + yy][xx];
                // zero-pad semantics per filter application: out-of-image rows stay 0
                s0[ly][xx] = (gy >= 0 && gy < 128) ? s : 0.f;
            }
        }
        __syncthreads();
    }
    // valid rows: ly in [HALO, HALO+BAND)
    float lmn = 3.4e38f, lmx = -3.4e38f;
    float* op = g_u2 + (size_t)b * HW + band * BAND * 128;
    for (int i = tid; i < BAND * 128; i += 256) {
        int ly = HALO + (i >> 7), xx = i & 127;
        float v = s0[ly][xx];
        op[i] = v;
        lmn = fminf(lmn, v); lmx = fmaxf(lmx, v);
    }
    atomicMin(&smn, __float_as_uint(lmn));
    atomicMax(&smx, __float_as_uint(lmx));
    __syncthreads();
    if (tid == 0) { atomicMin(&g_minb, smn); atomicMax(&g_maxb, smx); }
}

// ---------------- launch ----------------
extern "C" void kernel_launch(void* const* d_in, const int* in_sizes, int n_in,
                              void* d_out, int out_size) {
    const float* x     = (const float*)d_in[0];
    const float* Wproj = (const float*)d_in[1];
    const float* gamma = (const float*)d_in[2];
    const float* beta  = (const float*)d_in[3];
    const float* Wconv = (const float*)d_in[4];
    const float* bconv = (const float*)d_in[5];
    const float* Wmean = (const float*)d_in[6];
    const float* Wstd  = (const float*)d_in[7];
    const float* eps1  = (const float*)d_in[8];
    const float* eps50 = (const float*)d_in[9];
    const float* randu = (const float*)d_in[10];
    float* out = (float*)d_out;

    cudaFuncSetAttribute(k_gemm<1>, cudaFuncAttributeMaxDynamicSharedMemorySize, SMEM_GEMM);
    cudaFuncSetAttribute(k_gemm<2>, cudaFuncAttributeMaxDynamicSharedMemorySize, SMEM_GEMM);

    k_init<<<1, 256>>>();
    k_prep_w<<<512, 256>>>(Wproj, Wconv);
    k_gemm<1><<<NTOT / 128, 256, SMEM_GEMM>>>(x, nullptr, nullptr, nullptr);
    k_bnfin<<<1, 256>>>(gamma, beta);
    k_fuse<<<NTOT / 256, 256>>>(Wmean, Wstd, eps1, eps50, out);
    k_box<<<dim3(Bb, Bb), 256>>>();
    k_gemm<2><<<NTOT / 128, 256, SMEM_GEMM>>>(nullptr, out, bconv, randu);
}

// round 9
// speedup vs baseline: 2.8830x; 1.0945x over previous
#include <cuda_runtime.h>
#include <cuda_fp16.h>
#include <math.h>
#include <stdint.h>

#define Cc 256
#define HW 16384
#define Bb 8
#define CHW (Cc*HW)
#define NTOT (Bb*HW)
#define TOTAL (Bb*CHW)
#define PROB_OFF TOTAL
#define NS 50

#define STG 24576            // bytes per stage: A 16KB (2 parts) + B 8KB (G1) / 4KB (G2)
#define FAC_OFF (2*STG)      // 49152
#define BIAS_OFF (FAC_OFF+512)
#define BNA_OFF (BIAS_OFF+1024)
#define BNB_OFF (BNA_OFF+1024)
#define SMEM_GEMM (BNB_OFF+1024)

// ---------------- device globals ----------------
__device__ float g_h[TOTAL];                 // h pre-BN, [ch][P] fp32
__device__ __half g_B2[TOTAL];               // relu(bn(h)) fp16, pre-swizzled chunk tiles
__device__ __half g_wA[2*2*Cc*Cc];           // weights: [gemm][part][chunk][4096]
__device__ float g_sum[Cc], g_sumsq[Cc], g_bna[Cc], g_bnb[Cc];
__device__ float g_u[NTOT], g_u2[NTOT];
__device__ unsigned int g_minb, g_maxb;

union H8 { __half h[8]; uint4 v; };

__device__ __forceinline__ uint32_t s2u(const void* p) {
    uint32_t a;
    asm("{ .reg .u64 t; cvta.to.shared.u64 t, %1; cvt.u32.u64 %0, t; }" : "=r"(a) : "l"(p));
    return a;
}
__device__ __forceinline__ void cpa16(uint32_t dst, const void* src) {
    asm volatile("cp.async.cg.shared.global [%0], [%1], 16;" :: "r"(dst), "l"(src));
}
__device__ __forceinline__ void ldmx4(uint32_t& a0, uint32_t& a1, uint32_t& a2, uint32_t& a3, uint32_t ad) {
    asm volatile("ldmatrix.sync.aligned.m8n8.x4.shared.b16 {%0,%1,%2,%3}, [%4];"
                 : "=r"(a0), "=r"(a1), "=r"(a2), "=r"(a3) : "r"(ad));
}
__device__ __forceinline__ void ldmx2(uint32_t& b0, uint32_t& b1, uint32_t ad) {
    asm volatile("ldmatrix.sync.aligned.m8n8.x2.shared.b16 {%0,%1}, [%2];"
                 : "=r"(b0), "=r"(b1) : "r"(ad));
}
__device__ __forceinline__ void mma16816(float* d, const uint32_t* a, uint32_t b0, uint32_t b1) {
    asm volatile("mma.sync.aligned.m16n8k16.row.col.f32.f16.f16.f32 "
                 "{%0,%1,%2,%3}, {%4,%5,%6,%7}, {%8,%9}, {%0,%1,%2,%3};"
                 : "+f"(d[0]), "+f"(d[1]), "+f"(d[2]), "+f"(d[3])
                 : "r"(a[0]), "r"(a[1]), "r"(a[2]), "r"(a[3]), "r"(b0), "r"(b1));
}

// ---------------- init ----------------
__global__ void k_init() {
    int t = threadIdx.x;
    if (t < Cc) { g_sum[t] = 0.f; g_sumsq[t] = 0.f; }
    if (t == 0) { g_minb = 0xFFFFFFFFu; g_maxb = 0u; }
}

// ---------------- weight prep: 2-way fp16 split, chunked+swizzled ----------------
__global__ void k_prep_w(const float* __restrict__ Wp, const float* __restrict__ Wc) {
    int idx = blockIdx.x * blockDim.x + threadIdx.x;   // 0..131071
    int g = idx >> 16, ch = (idx >> 8) & 255, k = idx & 255;
    float w = (g ? Wc : Wp)[ch * Cc + k];
    __half H = __float2half_rn(w);
    __half L = __float2half_rn(w - __half2float(H));
    int kc = k >> 4, kk = k & 15;
    int unit = ((kk >> 3) ^ (ch >> 2)) & 1;
    int elem = (ch * 32 + unit * 16 + (kk & 7) * 2) >> 1;
    size_t base = (size_t)((g * 2) * 16 + kc) * 4096 + elem;
    g_wA[base]         = H;
    g_wA[base + 65536] = L;     // part stride = 16 chunks * 4096
}

// ---------------- mma.sync GEMM: tile 256ch x 128pix, K=256 in 16 chunks ----------------
// G=1: B = x fp32 (2-way fp16 split, 3 terms), epilogue -> g_h + BN stats
// G=2: B = g_B2 fp16 via cp.async (2 terms: AhBh+AlBh), epilogue -> out with bias + (1-u)*mask
template<int G>
__global__ __launch_bounds__(256, 1)
void k_gemm(const float* __restrict__ x, float* __restrict__ out,
            const float* __restrict__ bconv, const float* __restrict__ randu) {
    extern __shared__ __align__(16) char sm[];
    const uint32_t sb = s2u(sm);
    const int t = threadIdx.x, wid = t >> 5, lane = t & 31;
    const int P0 = blockIdx.x * 128;

    const int ch0 = (wid >> 1) * 64;
    const int pix0w = (wid & 1) * 64;
    const int aRow = lane & 15, aUnit = lane >> 4;
    const int l15 = lane & 15;
    const int bRowOff = l15 & 7, bUnit = (l15 >> 3) & 1;
    const int px = t & 127, kg = t >> 7;       // G1 B loader: pixel + k-half

    float* s_fac  = (float*)(sm + FAC_OFF);
    float* s_bias = (float*)(sm + BIAS_OFF);
    float* s_bna  = (float*)(sm + BNA_OFF);
    float* s_bnb  = (float*)(sm + BNB_OFF);
    if (G == 2) {
        if (t < 128) {
            float mn = __uint_as_float(g_minb), mx = __uint_as_float(g_maxb);
            float un = (g_u2[P0 + t] - mn) / (mx - mn);
            s_fac[t] = (1.f - un) * ((un < randu[P0 + t]) ? 1.f : 0.f);
        }
        s_bias[t] = bconv[t];
        __syncthreads();
    }

    float d[4][8][4];
#pragma unroll
    for (int i = 0; i < 4; i++)
#pragma unroll
        for (int j = 0; j < 8; j++)
#pragma unroll
            for (int e = 0; e < 4; e++) d[i][j][e] = 0.f;

    float bf[8];
    const float* xs = x + (size_t)(P0 >> 14) * CHW + (P0 & 16383) + px;

#define ISSUE_A(cc, so) do { \
    _Pragma("unroll") \
    for (int i = 0; i < 4; i++) { \
        int u = t + i * 256; \
        int p = u >> 9, w = u & 511; \
        const char* src = (const char*)g_wA + (size_t)(((G - 1) * 2 + p) * 16 + (cc)) * 8192 + w * 16; \
        cpa16(sb + (so) + p * 8192 + w * 16, src); \
    } \
    if (G == 2) { \
        const char* srcb = (const char*)g_B2 + ((size_t)(blockIdx.x * 16 + (cc)) * 4096) + t * 16; \
        cpa16(sb + (so) + 16384 + t * 16, srcb); \
    } \
    asm volatile("cp.async.commit_group;"); \
} while (0)

#define LOAD_B(cc) do { \
    if (G == 1) { \
        _Pragma("unroll") \
        for (int e = 0; e < 8; e++) bf[e] = xs[(size_t)((cc) * 16 + kg * 8 + e) * HW]; \
    } \
} while (0)

#define STORE_B(so) do { \
    if (G == 1) { \
        H8 u0, u1; \
        _Pragma("unroll") \
        for (int e = 0; e < 8; e++) { \
            u0.h[e] = __float2half_rn(bf[e]); \
            u1.h[e] = __float2half_rn(bf[e] - __half2float(u0.h[e])); \
        } \
        int u2 = (kg ^ (px >> 2)) & 1; \
        char* dst = sm + (so) + 16384 + px * 32 + u2 * 16; \
        *(uint4*)(dst) = u0.v; \
        *(uint4*)(dst + 4096) = u1.v; \
    } \
} while (0)

    // prologue: chunk 0
    LOAD_B(0);
    ISSUE_A(0, 0);
    STORE_B(0);
    asm volatile("cp.async.wait_group 0;");
    __syncthreads();

    for (int c = 0; c < 16; c++) {
        const uint32_t so_cur = (c & 1) * STG;
        const uint32_t so_nxt = ((c + 1) & 1) * STG;
        if (c < 15) {
            ISSUE_A(c + 1, so_nxt);
            LOAD_B(c + 1);
        }
        // ---- MMA on current stage ----
        {
            uint32_t Ast = sb + so_cur;
            uint32_t Bst = Ast + 16384;
            constexpr int NPB = (G == 1) ? 2 : 1;
            uint32_t Bf[NPB][8][2];
#pragma unroll
            for (int p = 0; p < NPB; p++)
#pragma unroll
                for (int nt = 0; nt < 8; nt++) {
                    int row = pix0w + nt * 8 + bRowOff;
                    uint32_t ad = Bst + p * 4096 + row * 32 + (((bUnit ^ (row >> 2)) & 1) << 4);
                    ldmx2(Bf[p][nt][0], Bf[p][nt][1], ad);
                }
#pragma unroll
            for (int mt = 0; mt < 4; mt++) {
#pragma unroll
                for (int pa = 0; pa < 2; pa++) {
                    int row = ch0 + mt * 16 + aRow;
                    uint32_t ad = Ast + pa * 8192 + row * 32 + (((aUnit ^ (row >> 2)) & 1) << 4);
                    uint32_t a[4];
                    ldmx4(a[0], a[1], a[2], a[3], ad);
                    const int nb = (G == 1) ? (2 - pa) : 1;   // G1: AhBh,AhBl,AlBh  G2: AhBh,AlBh
#pragma unroll
                    for (int pb = 0; pb < NPB; pb++) {
                        if (pb >= nb) break;
#pragma unroll
                        for (int nt = 0; nt < 8; nt++)
                            mma16816(d[mt][nt], a, Bf[pb][nt][0], Bf[pb][nt][1]);
                    }
                }
            }
        }
        if (c < 15) {
            STORE_B(so_nxt);
            asm volatile("cp.async.wait_group 0;");
        }
        __syncthreads();
    }

    // ---- epilogue ----
    const int rq = lane >> 2, q = lane & 3;
    if (G == 1) {
        float* s_sum = (float*)sm;
        float* s_sq = s_sum + 256;
        s_sum[t] = 0.f; s_sq[t] = 0.f;
        __syncthreads();
#pragma unroll
        for (int mt = 0; mt < 4; mt++) {
            int c_0 = ch0 + mt * 16 + rq, c_1 = c_0 + 8;
            float s0 = 0.f, q0 = 0.f, s1 = 0.f, q1 = 0.f;
#pragma unroll
            for (int nt = 0; nt < 8; nt++) {
                float v0 = d[mt][nt][0], v1 = d[mt][nt][1];
                float v2 = d[mt][nt][2], v3 = d[mt][nt][3];
                size_t PP = (size_t)P0 + pix0w + nt * 8 + q * 2;
                *(float2*)&g_h[(size_t)c_0 * NTOT + PP] = make_float2(v0, v1);
                *(float2*)&g_h[(size_t)c_1 * NTOT + PP] = make_float2(v2, v3);
                s0 += v0 + v1; q0 += v0 * v0 + v1 * v1;
                s1 += v2 + v3; q1 += v2 * v2 + v3 * v3;
            }
#pragma unroll
            for (int o = 1; o <= 2; o <<= 1) {
                s0 += __shfl_xor_sync(0xFFFFFFFFu, s0, o);
                q0 += __shfl_xor_sync(0xFFFFFFFFu, q0, o);
                s1 += __shfl_xor_sync(0xFFFFFFFFu, s1, o);
                q1 += __shfl_xor_sync(0xFFFFFFFFu, q1, o);
            }
            if (q == 0) {
                atomicAdd(&s_sum[c_0], s0); atomicAdd(&s_sq[c_0], q0);
                atomicAdd(&s_sum[c_1], s1); atomicAdd(&s_sq[c_1], q1);
            }
        }
        __syncthreads();
        atomicAdd(&g_sum[t], s_sum[t]);
        atomicAdd(&g_sumsq[t], s_sq[t]);
    } else {
        const size_t obase = (size_t)(P0 >> 14) * CHW + (P0 & 16383);
#pragma unroll
        for (int mt = 0; mt < 4; mt++) {
            int c_0 = ch0 + mt * 16 + rq, c_1 = c_0 + 8;
            float b0 = s_bias[c_0], b1 = s_bias[c_1];
#pragma unroll
            for (int nt = 0; nt < 8; nt++) {
                int pixL = pix0w + nt * 8 + q * 2;
                float f0 = s_fac[pixL], f1 = s_fac[pixL + 1];
                *(float2*)&out[obase + (size_t)c_0 * HW + pixL] =
                    make_float2((d[mt][nt][0] + b0) * f0, (d[mt][nt][1] + b0) * f1);
                *(float2*)&out[obase + (size_t)c_1 * HW + pixL] =
                    make_float2((d[mt][nt][2] + b1) * f0, (d[mt][nt][3] + b1) * f1);
            }
        }
    }
#undef ISSUE_A
#undef LOAD_B
#undef STORE_B
}

// ---------------- BN finalize ----------------
__global__ void k_bnfin(const float* __restrict__ gamma, const float* __restrict__ beta) {
    int c = threadIdx.x;
    float n = (float)NTOT;
    float mu = g_sum[c] / n;
    float var = fmaxf(g_sumsq[c] / n - mu * mu, 0.f);
    float a = gamma[c] * rsqrtf(var + 1e-5f);
    g_bna[c] = a; g_bnb[c] = beta[c] - mu * a;
}

// ---------------- fused: BN+ReLU -> g_B2 (fp16 tiled), mean/logvar GEMV, prob_x, u ----------------
__global__ void k_fuse(const float* __restrict__ Wm, const float* __restrict__ Ws,
                       const float* __restrict__ eps1, const float* __restrict__ eps50,
                       float* __restrict__ out) {
    __shared__ float s_a[Cc], s_b[Cc], s_wm[Cc], s_ws[Cc];
    int t = threadIdx.x;
    s_a[t] = g_bna[t]; s_b[t] = g_bnb[t]; s_wm[t] = Wm[t]; s_ws[t] = Ws[t];
    __syncthreads();
    int P = blockIdx.x * 256 + t;
    int tile = P >> 7, px = P & 127;
    float m = 0.f, lv = 0.f;
#pragma unroll 4
    for (int cc = 0; cc < 16; cc++) {
#pragma unroll
        for (int kg = 0; kg < 2; kg++) {
            H8 u0;
#pragma unroll
            for (int e = 0; e < 8; e++) {
                int ch = cc * 16 + kg * 8 + e;
                float v = g_h[(size_t)ch * NTOT + P];
                float r = fmaxf(fmaf(s_a[ch], v, s_b[ch]), 0.f);
                m = fmaf(s_wm[ch], r, m);
                lv = fmaf(s_ws[ch], r, lv);
                u0.h[e] = __float2half_rn(r);
            }
            int u2 = (kg ^ (px >> 2)) & 1;
            *(uint4*)(g_B2 + (size_t)(tile * 16 + cc) * 2048 + px * 16 + u2 * 8) = u0.v;
        }
    }
    float stdv = __expf(0.5f * lv);
    out[PROB_OFF + P] = fmaf(eps1[P], stdv, m);
    int b = P >> 14, hw = P & (HW - 1);
    const float* e = eps50 + (size_t)b * NS * HW + hw;
    float v[NS], s = 0.f;
#pragma unroll
    for (int i = 0; i < NS; i++) {
        float tt = fmaf(e[(size_t)i * HW], stdv, m);
        float pv = __fdividef(1.f, 1.f + __expf(-tt));
        v[i] = pv; s += pv;
    }
    float mm = s * (1.f / NS), ss = 0.f;
#pragma unroll
    for (int i = 0; i < NS; i++) { float dd = v[i] - mm; ss = fmaf(dd, dd, ss); }
    g_u[P] = ss * (1.f / (NS - 1));
}

// ---------------- 3x 7x7 box filter, banded (64 blocks), + global min/max ----------------
#define BAND 16
#define HALO 9
#define LROWS (BAND + 2*HALO)   // 34
__global__ void k_box() {
    __shared__ float s0[LROWS][128], s1[LROWS][128];
    __shared__ unsigned int smn, smx;
    const int band = blockIdx.x, b = blockIdx.y;
    const int r0 = band * BAND - HALO;     // global row of ly=0
    const int tid = threadIdx.x;
    if (tid == 0) { smn = 0xFFFFFFFFu; smx = 0u; }
    const float* up = g_u + (size_t)b * HW;
    for (int i = tid; i < LROWS * 128; i += 256) {
        int ly = i >> 7, xx = i & 127;
        int gy = r0 + ly;
        s0[ly][xx] = (gy >= 0 && gy < 128) ? up[(gy << 7) + xx] : 0.f;
    }
    __syncthreads();
    int lo = 0, hi = LROWS;
    for (int it = 0; it < 3; it++) {
        for (int i = tid; i < LROWS * 128; i += 256) {
            int ly = i >> 7, xx = i & 127;
            if (ly >= lo && ly < hi) {
                int x0 = xx - 3 < 0 ? 0 : xx - 3;
                int x1 = xx + 3 > 127 ? 127 : xx + 3;
                float s = 0.f;
                for (int x2 = x0; x2 <= x1; x2++) s += s0[ly][x2];
                s1[ly][xx] = s;
            }
        }
        __syncthreads();
        lo += 3; hi -= 3;
        for (int i = tid; i < LROWS * 128; i += 256) {
            int ly = i >> 7, xx = i & 127;
            if (ly >= lo && ly < hi) {
                int gy = r0 + ly;
                float s = 0.f;
#pragma unroll
                for (int yy = -3; yy <= 3; yy++) s += s1[ly + yy][xx];
                s0[ly][xx] = (gy >= 0 && gy < 128) ? s : 0.f;   // per-iter zero pad
            }
        }
        __syncthreads();
    }
    float lmn = 3.4e38f, lmx = -3.4e38f;
    float* op = g_u2 + (size_t)b * HW + band * BAND * 128;
    for (int i = tid; i < BAND * 128; i += 256) {
        int ly = HALO + (i >> 7), xx = i & 127;
        float v = s0[ly][xx];
        op[i] = v;
        lmn = fminf(lmn, v); lmx = fmaxf(lmx, v);
    }
    atomicMin(&smn, __float_as_uint(lmn));
    atomicMax(&smx, __float_as_uint(lmx));
    __syncthreads();
    if (tid == 0) { atomicMin(&g_minb, smn); atomicMax(&g_maxb, smx); }
}

// ---------------- launch ----------------
extern "C" void kernel_launch(void* const* d_in, const int* in_sizes, int n_in,
                              void* d_out, int out_size) {
    const float* x     = (const float*)d_in[0];
    const float* Wproj = (const float*)d_in[1];
    const float* gamma = (const float*)d_in[2];
    const float* beta  = (const float*)d_in[3];
    const float* Wconv = (const float*)d_in[4];
    const float* bconv = (const float*)d_in[5];
    const float* Wmean = (const float*)d_in[6];
    const float* Wstd  = (const float*)d_in[7];
    const float* eps1  = (const float*)d_in[8];
    const float* eps50 = (const float*)d_in[9];
    const float* randu = (const float*)d_in[10];
    float* out = (float*)d_out;

    cudaFuncSetAttribute(k_gemm<1>, cudaFuncAttributeMaxDynamicSharedMemorySize, SMEM_GEMM);
    cudaFuncSetAttribute(k_gemm<2>, cudaFuncAttributeMaxDynamicSharedMemorySize, SMEM_GEMM);

    k_init<<<1, 256>>>();
    k_prep_w<<<512, 256>>>(Wproj, Wconv);
    k_gemm<1><<<NTOT / 128, 256, SMEM_GEMM>>>(x, nullptr, nullptr, nullptr);
    k_bnfin<<<1, 256>>>(gamma, beta);
    k_fuse<<<NTOT / 256, 256>>>(Wmean, Wstd, eps1, eps50, out);
    k_box<<<dim3(Bb, Bb), 256>>>();
    k_gemm<2><<<NTOT / 128, 256, SMEM_GEMM>>>(nullptr, out, bconv, randu);
}